// round 2
// baseline (speedup 1.0000x reference)
#include <cuda_runtime.h>
#include <math.h>

#define SEQ   2048
#define BATCH 2
#define NHEADS 16
#define HDIM  64
#define MDIM  1024
#define TOKENS (BATCH*SEQ)   // 4096

// ---------------- scratch (device globals: no allocations allowed) ----------
__device__ float g_q[BATCH*NHEADS*SEQ*HDIM];   // 16 MB, (B,H,N,D), LN'd + scaled
__device__ float g_k[BATCH*NHEADS*SEQ*HDIM];   // 16 MB, (B,H,N,D), LN'd
__device__ float g_v[BATCH*NHEADS*SEQ*HDIM];   // 16 MB, (B,H,N,D)
__device__ float g_ao[(size_t)TOKENS*MDIM];    // 16 MB, (B,N,C) attention output
__device__ int   g_mask_kind;                  // 0=int32, 1=uint8, 2=float32

// ---------------- mask dtype probe (deterministic, data-driven) -------------
__global__ void probe_mask_kernel(const unsigned int* __restrict__ m)
{
    __shared__ int s_ni, s_nf;
    if (threadIdx.x == 0) { s_ni = 0; s_nf = 0; }
    __syncthreads();
    int ni = 0, nf = 0;
    for (int i = threadIdx.x; i < 4096; i += 256) {
        unsigned w = m[i];
        if (w > 1u) ni = 1;                         // not an int32 0/1 word
        if (w != 0u && w != 0x3F800000u) nf = 1;    // not a float 0.0/1.0 word
    }
    if (ni) atomicOr(&s_ni, 1);
    if (nf) atomicOr(&s_nf, 1);
    __syncthreads();
    if (threadIdx.x == 0)
        g_mask_kind = (s_ni == 0) ? 0 : (s_nf == 0) ? 2 : 1;
}

// ---------------- kernel 1: QKV GEMM + fused per-head layernorm -------------
// C[4096,3072] = X[4096,1024] @ W[3072,1024]^T
// col block n0..n0+63 == one (s,h): s = n0/1024 (0=q,1=k,2=v), h = (n0%1024)/64
__global__ __launch_bounds__(256) void qkv_gemm_ln_kernel(
    const float* __restrict__ X, const float* __restrict__ W,
    const float* __restrict__ qw, const float* __restrict__ qb,
    const float* __restrict__ kw, const float* __restrict__ kb)
{
    __shared__ float sm[128*68];           // 34.8 KB; GEMM stage + epilogue tile
    float* As = sm;                        // [16][128] k-major
    float* Bs = sm + 16*128;               // [16][64]  k-major
    const int tid = threadIdx.x;
    const int m0 = blockIdx.y * 128;
    const int n0 = blockIdx.x * 64;
    const int ty = tid >> 4, tx = tid & 15;

    float acc[8][4];
#pragma unroll
    for (int i = 0; i < 8; i++)
#pragma unroll
        for (int j = 0; j < 4; j++) acc[i][j] = 0.f;

    for (int k0 = 0; k0 < MDIM; k0 += 16) {
        __syncthreads();
#pragma unroll
        for (int u = 0; u < 2; u++) {
            int f = tid*2 + u;
            int row = f >> 2, c4 = (f & 3) * 4;
            float4 a = *(const float4*)(X + (size_t)(m0+row)*MDIM + k0 + c4);
            As[(c4+0)*128 + row] = a.x;
            As[(c4+1)*128 + row] = a.y;
            As[(c4+2)*128 + row] = a.z;
            As[(c4+3)*128 + row] = a.w;
        }
        {
            int row = tid >> 2, c4 = (tid & 3) * 4;
            float4 v = *(const float4*)(W + (size_t)(n0+row)*MDIM + k0 + c4);
            Bs[(c4+0)*64 + row] = v.x;
            Bs[(c4+1)*64 + row] = v.y;
            Bs[(c4+2)*64 + row] = v.z;
            Bs[(c4+3)*64 + row] = v.w;
        }
        __syncthreads();
#pragma unroll
        for (int k = 0; k < 16; k++) {
            float a[8], b[4];
            *(float4*)(a)   = *(const float4*)(As + k*128 + ty*8);
            *(float4*)(a+4) = *(const float4*)(As + k*128 + ty*8 + 4);
            *(float4*)(b)   = *(const float4*)(Bs + k*64 + tx*4);
#pragma unroll
            for (int i = 0; i < 8; i++)
#pragma unroll
                for (int j = 0; j < 4; j++)
                    acc[i][j] = fmaf(a[i], b[j], acc[i][j]);
        }
    }
    __syncthreads();
    // stash tile to smem [128][68] for cross-thread row reductions
#pragma unroll
    for (int i = 0; i < 8; i++)
        *(float4*)(sm + (ty*8+i)*68 + tx*4) = *(float4*)(acc[i]);
    __syncthreads();

    const int s = n0 >> 10;
    const int h = (n0 & 1023) >> 6;
    const int warp = tid >> 5, lane = tid & 31;
    for (int rr = 0; rr < 16; rr++) {
        int row = warp*16 + rr;
        int gm  = m0 + row;
        int bb  = gm >> 11, n = gm & 2047;
        float v1 = sm[row*68 + lane];
        float v2 = sm[row*68 + lane + 32];
        size_t base = (((size_t)(bb*NHEADS + h))*SEQ + n)*HDIM;
        if (s == 2) {
            g_v[base + lane] = v1;
            g_v[base + lane + 32] = v2;
        } else {
            float sum = v1 + v2, sq = v1*v1 + v2*v2;
#pragma unroll
            for (int o = 16; o; o >>= 1) {
                sum += __shfl_xor_sync(0xffffffffu, sum, o);
                sq  += __shfl_xor_sync(0xffffffffu, sq,  o);
            }
            float mean = sum * (1.f/64.f);
            float var  = sq  * (1.f/64.f) - mean*mean;
            float rstd = rsqrtf(var + 1e-5f);
            if (s == 0) {  // q: layernorm then * D^-0.5
                float y1 = ((v1-mean)*rstd*qw[lane]    + qb[lane])    * 0.125f;
                float y2 = ((v2-mean)*rstd*qw[lane+32] + qb[lane+32]) * 0.125f;
                g_q[base + lane] = y1;  g_q[base + lane + 32] = y2;
            } else {       // k: layernorm
                float y1 = (v1-mean)*rstd*kw[lane]    + kb[lane];
                float y2 = (v2-mean)*rstd*kw[lane+32] + kb[lane+32];
                g_k[base + lane] = y1;  g_k[base + lane + 32] = y2;
            }
        }
    }
}

// ---------------- kernel 2: flash attention ---------------------------------
// block = (qtile of 64, head, batch); 256 threads; 64 KB dynamic smem
__global__ __launch_bounds__(256) void flash_attn_kernel(const void* __restrict__ maskp)
{
    extern __shared__ float fsm[];
    float* qs  = fsm;            // [64 row][64 d]
    float* kst = fsm + 4096;     // [64 d][64 key], XOR-swizzled (key ^ (d&60))
    float* vs  = fsm + 8192;     // [64 key][64 d]
    float* ps  = fsm + 12288;    // [64 row][64 col]
    const int tid = threadIdx.x;
    const int q0 = blockIdx.x * 64;
    const int h  = blockIdx.y;
    const int b  = blockIdx.z;
    const size_t bh = (size_t)(b*NHEADS + h) * SEQ * HDIM;
    const float* Q = g_q + bh;
    const float* K = g_k + bh;
    const float* V = g_v + bh;
    const int ty = tid >> 4, tx = tid & 15;   // ty: 4 rows each, tx: 4 cols/dims each

#pragma unroll
    for (int u = 0; u < 4; u++) {
        int f = tid + u*256;
        int row = f >> 4, d = (f & 15) * 4;
        *(float4*)(qs + row*64 + d) = *(const float4*)(Q + (size_t)(q0+row)*HDIM + d);
    }

    float m[4], l[4], o[4][4];
#pragma unroll
    for (int i = 0; i < 4; i++) {
        m[i] = -INFINITY; l[i] = 0.f;
#pragma unroll
        for (int j = 0; j < 4; j++) o[i][j] = 0.f;
    }
    const int kind = g_mask_kind;
    const int*           mi = (const int*)maskp;
    const unsigned char* mb = (const unsigned char*)maskp;
    const float*         mf = (const float*)maskp;
    const size_t mbase0 = (size_t)b * SEQ * SEQ;

    for (int kt = 0; kt < SEQ/64; kt++) {
        __syncthreads();
#pragma unroll
        for (int u = 0; u < 4; u++) {
            int f = tid + u*256;
            int key = f >> 4, d = (f & 15) * 4;
            float4 kv = *(const float4*)(K + (size_t)(kt*64+key)*HDIM + d);
            int sk = key ^ d;                  // d is a multiple of 4, d<=60
            kst[(d+0)*64 + sk] = kv.x;
            kst[(d+1)*64 + sk] = kv.y;
            kst[(d+2)*64 + sk] = kv.z;
            kst[(d+3)*64 + sk] = kv.w;
            *(float4*)(vs + key*64 + d) = *(const float4*)(V + (size_t)(kt*64+key)*HDIM + d);
        }
        __syncthreads();

        float s[4][4];
#pragma unroll
        for (int i = 0; i < 4; i++)
#pragma unroll
            for (int j = 0; j < 4; j++) s[i][j] = 0.f;

#pragma unroll
        for (int d = 0; d < 64; d += 4) {
            float a4[4][4], k4[4][4];
#pragma unroll
            for (int i = 0; i < 4; i++)
                *(float4*)a4[i] = *(const float4*)(qs + (ty*4+i)*64 + d);
#pragma unroll
            for (int dd = 0; dd < 4; dd++)
                *(float4*)k4[dd] = *(const float4*)(kst + (d+dd)*64 + ((tx*4) ^ d));
#pragma unroll
            for (int i = 0; i < 4; i++)
#pragma unroll
                for (int dd = 0; dd < 4; dd++)
#pragma unroll
                    for (int j = 0; j < 4; j++)
                        s[i][j] = fmaf(a4[i][dd], k4[dd][j], s[i][j]);
        }

#pragma unroll
        for (int i = 0; i < 4; i++) {
            int qr = q0 + ty*4 + i;
            size_t midx = mbase0 + (size_t)qr*SEQ + (size_t)kt*64 + tx*4;
            bool mk[4];
            if (kind == 0)      { for (int j = 0; j < 4; j++) mk[j] = mi[midx+j] != 0; }
            else if (kind == 1) { for (int j = 0; j < 4; j++) mk[j] = mb[midx+j] != 0; }
            else                { for (int j = 0; j < 4; j++) mk[j] = mf[midx+j] != 0.f; }
#pragma unroll
            for (int j = 0; j < 4; j++) if (mk[j]) s[i][j] = -1e30f;

            float tmax = fmaxf(fmaxf(s[i][0], s[i][1]), fmaxf(s[i][2], s[i][3]));
#pragma unroll
            for (int off = 8; off; off >>= 1)
                tmax = fmaxf(tmax, __shfl_xor_sync(0xffffffffu, tmax, off));
            float mn   = fmaxf(m[i], tmax);
            float corr = __expf(m[i] - mn);
            m[i] = mn;
            float ts = 0.f;
#pragma unroll
            for (int j = 0; j < 4; j++) {
                float p = mk[j] ? 0.f : __expf(s[i][j] - mn);
                s[i][j] = p; ts += p;
            }
#pragma unroll
            for (int off = 8; off; off >>= 1)
                ts += __shfl_xor_sync(0xffffffffu, ts, off);
            l[i] = l[i]*corr + ts;
#pragma unroll
            for (int j = 0; j < 4; j++) o[i][j] *= corr;
            *(float4*)(ps + (ty*4+i)*64 + tx*4) =
                make_float4(s[i][0], s[i][1], s[i][2], s[i][3]);
        }
        __syncthreads();

#pragma unroll
        for (int jk = 0; jk < 64; jk += 4) {
            float p4[4][4], v4[4][4];
#pragma unroll
            for (int i = 0; i < 4; i++)
                *(float4*)p4[i] = *(const float4*)(ps + (ty*4+i)*64 + jk);
#pragma unroll
            for (int jj = 0; jj < 4; jj++)
                *(float4*)v4[jj] = *(const float4*)(vs + (jk+jj)*64 + tx*4);
#pragma unroll
            for (int i = 0; i < 4; i++)
#pragma unroll
                for (int jj = 0; jj < 4; jj++)
#pragma unroll
                    for (int j = 0; j < 4; j++)
                        o[i][j] = fmaf(p4[i][jj], v4[jj][j], o[i][j]);
        }
    }

#pragma unroll
    for (int i = 0; i < 4; i++) {
        float inv = 1.f / l[i];
        float4 ov = make_float4(o[i][0]*inv, o[i][1]*inv, o[i][2]*inv, o[i][3]*inv);
        size_t oi = ((size_t)b*SEQ + q0 + ty*4 + i)*MDIM + h*HDIM + tx*4;
        *(float4*)(g_ao + oi) = ov;
    }
}

// ---------------- kernel 3: output projection + bias ------------------------
// out[4096,1024] = g_ao[4096,1024] @ proj_w[1024,1024]^T + proj_b
__global__ __launch_bounds__(256) void proj_gemm_kernel(
    const float* __restrict__ W, const float* __restrict__ bias,
    float* __restrict__ out)
{
    __shared__ float sm[16*128 + 16*64];
    float* As = sm;
    float* Bs = sm + 16*128;
    const int tid = threadIdx.x;
    const int m0 = blockIdx.y * 128;
    const int n0 = blockIdx.x * 64;
    const int ty = tid >> 4, tx = tid & 15;

    float acc[8][4];
#pragma unroll
    for (int i = 0; i < 8; i++)
#pragma unroll
        for (int j = 0; j < 4; j++) acc[i][j] = 0.f;

    for (int k0 = 0; k0 < MDIM; k0 += 16) {
        __syncthreads();
#pragma unroll
        for (int u = 0; u < 2; u++) {
            int f = tid*2 + u;
            int row = f >> 2, c4 = (f & 3) * 4;
            float4 a = *(const float4*)(g_ao + (size_t)(m0+row)*MDIM + k0 + c4);
            As[(c4+0)*128 + row] = a.x;
            As[(c4+1)*128 + row] = a.y;
            As[(c4+2)*128 + row] = a.z;
            As[(c4+3)*128 + row] = a.w;
        }
        {
            int row = tid >> 2, c4 = (tid & 3) * 4;
            float4 v = *(const float4*)(W + (size_t)(n0+row)*MDIM + k0 + c4);
            Bs[(c4+0)*64 + row] = v.x;
            Bs[(c4+1)*64 + row] = v.y;
            Bs[(c4+2)*64 + row] = v.z;
            Bs[(c4+3)*64 + row] = v.w;
        }
        __syncthreads();
#pragma unroll
        for (int k = 0; k < 16; k++) {
            float a[8], b[4];
            *(float4*)(a)   = *(const float4*)(As + k*128 + ty*8);
            *(float4*)(a+4) = *(const float4*)(As + k*128 + ty*8 + 4);
            *(float4*)(b)   = *(const float4*)(Bs + k*64 + tx*4);
#pragma unroll
            for (int i = 0; i < 8; i++)
#pragma unroll
                for (int j = 0; j < 4; j++)
                    acc[i][j] = fmaf(a[i], b[j], acc[i][j]);
        }
    }

    float4 bs4 = *(const float4*)(bias + n0 + tx*4);
#pragma unroll
    for (int i = 0; i < 8; i++) {
        float4 ov = make_float4(acc[i][0]+bs4.x, acc[i][1]+bs4.y,
                                acc[i][2]+bs4.z, acc[i][3]+bs4.w);
        *(float4*)(out + (size_t)(m0+ty*8+i)*MDIM + n0 + tx*4) = ov;
    }
}

// ---------------- launch ----------------------------------------------------
extern "C" void kernel_launch(void* const* d_in, const int* in_sizes, int n_in,
                              void* d_out, int out_size)
{
    const float* x      = (const float*)d_in[0];
    const void*  mask   = d_in[1];
    const float* qkv_w  = (const float*)d_in[2];
    const float* q_nw   = (const float*)d_in[3];
    const float* q_nb   = (const float*)d_in[4];
    const float* k_nw   = (const float*)d_in[5];
    const float* k_nb   = (const float*)d_in[6];
    const float* proj_w = (const float*)d_in[7];
    const float* proj_b = (const float*)d_in[8];
    float* out = (float*)d_out;

    probe_mask_kernel<<<1, 256>>>((const unsigned int*)mask);

    qkv_gemm_ln_kernel<<<dim3(48, 32), 256>>>(x, qkv_w, q_nw, q_nb, k_nw, k_nb);

    cudaFuncSetAttribute(flash_attn_kernel,
                         cudaFuncAttributeMaxDynamicSharedMemorySize, 65536);
    flash_attn_kernel<<<dim3(32, NHEADS, BATCH), 256, 65536>>>(mask);

    proj_gemm_kernel<<<dim3(16, 32), 256>>>(proj_w, proj_b, out);
}

// round 3
// speedup vs baseline: 1.2681x; 1.2681x over previous
#include <cuda_runtime.h>
#include <cuda_bf16.h>
#include <math.h>

#define SEQ   2048
#define BATCH 2
#define NHEADS 16
#define HDIM  64
#define MDIM  1024
#define TOKENS (BATCH*SEQ)   // 4096

// ---------------- scratch (device globals: no allocations allowed) ----------
__device__ float g_q[BATCH*NHEADS*SEQ*HDIM];   // (B,H,N,D), LN'd + scaled
__device__ float g_k[BATCH*NHEADS*SEQ*HDIM];   // (B,H,N,D), LN'd
__device__ float g_v[BATCH*NHEADS*SEQ*HDIM];   // (B,H,N,D)
__device__ float g_ao[(size_t)TOKENS*MDIM];    // (B,N,C) attention output
__device__ int   g_mask_kind;                  // 0=int32, 1=uint8, 2=float32

// ---------------- helpers ----------------------------------------------------
__device__ __forceinline__ void cvt_pack(float x0, float x1, unsigned &h, unsigned &l)
{
    __nv_bfloat16 h0 = __float2bfloat16_rn(x0);
    __nv_bfloat16 h1 = __float2bfloat16_rn(x1);
    __nv_bfloat16 l0 = __float2bfloat16_rn(x0 - __bfloat162float(h0));
    __nv_bfloat16 l1 = __float2bfloat16_rn(x1 - __bfloat162float(h1));
    __nv_bfloat162 hp; hp.x = h0; hp.y = h1;
    __nv_bfloat162 lp; lp.x = l0; lp.y = l1;
    h = *reinterpret_cast<unsigned*>(&hp);
    l = *reinterpret_cast<unsigned*>(&lp);
}

__device__ __forceinline__ void mma_bf16(float* c, const unsigned* a, const unsigned* b)
{
    asm volatile(
        "mma.sync.aligned.m16n8k16.row.col.f32.bf16.bf16.f32 "
        "{%0,%1,%2,%3},{%4,%5,%6,%7},{%8,%9},{%0,%1,%2,%3};"
        : "+f"(c[0]), "+f"(c[1]), "+f"(c[2]), "+f"(c[3])
        : "r"(a[0]), "r"(a[1]), "r"(a[2]), "r"(a[3]), "r"(b[0]), "r"(b[1]));
}

// smem strides (uint32 pair elements), chosen so fragment LDS are conflict-free:
// bank = (stride*k2 + m) mod 32 with stride ≡ 4 (mod 32) -> 4*tg + group (all distinct)
#define SA 132      // A tile: [16 k2][128 m] stride 132
#define SB 68       // B tile: [16 k2][64 n]  stride 68
#define SM_U (2*16*SA + 2*16*SB)   // 6400 uint32 = 25600 B

// ---------------- mask dtype probe ------------------------------------------
__global__ void probe_mask_kernel(const unsigned int* __restrict__ m)
{
    __shared__ int s_ni, s_nf;
    if (threadIdx.x == 0) { s_ni = 0; s_nf = 0; }
    __syncthreads();
    int ni = 0, nf = 0;
    for (int i = threadIdx.x; i < 4096; i += 256) {
        unsigned w = m[i];
        if (w > 1u) ni = 1;
        if (w != 0u && w != 0x3F800000u) nf = 1;
    }
    if (ni) atomicOr(&s_ni, 1);
    if (nf) atomicOr(&s_nf, 1);
    __syncthreads();
    if (threadIdx.x == 0)
        g_mask_kind = (s_ni == 0) ? 0 : (s_nf == 0) ? 2 : 1;
}

// ---------------- kernel 1: QKV GEMM (bf16x3 mma) + fused layernorm ---------
// C[4096,3072] = X[4096,1024] @ W[3072,1024]^T ; n-block 64 == one (s,head)
__global__ __launch_bounds__(256, 2) void qkv_gemm_ln_kernel(
    const float* __restrict__ X, const float* __restrict__ W,
    const float* __restrict__ qw, const float* __restrict__ qb,
    const float* __restrict__ kw, const float* __restrict__ kb)
{
    __shared__ unsigned smu[SM_U];
    unsigned* Ah = smu;
    unsigned* Al = Ah + 16*SA;
    unsigned* Bh = Al + 16*SA;
    unsigned* Bl = Bh + 16*SB;

    const int tid = threadIdx.x;
    const int m0 = blockIdx.y * 128;
    const int n0 = blockIdx.x * 64;
    const int warp = tid >> 5, lane = tid & 31;
    const int warp_m = warp >> 1, warp_n = warp & 1;   // 4 x 2
    const int group = lane >> 2, tg = lane & 3;

    float acc[2][4][4];
#pragma unroll
    for (int mt = 0; mt < 2; mt++)
#pragma unroll
        for (int nt = 0; nt < 4; nt++)
#pragma unroll
            for (int j = 0; j < 4; j++) acc[mt][nt][j] = 0.f;

    for (int k0 = 0; k0 < MDIM; k0 += 32) {
        __syncthreads();
        // stage A: 128x32 floats -> hi/lo bf16 pairs (k-pair major)
#pragma unroll
        for (int u = 0; u < 4; u++) {
            int idx = tid + u*256;           // float4 index 0..1023
            int row = idx >> 3, kq = (idx & 7) * 4;
            float4 v = *(const float4*)(X + (size_t)(m0+row)*MDIM + k0 + kq);
            unsigned h0, l0, h1, l1;
            cvt_pack(v.x, v.y, h0, l0);
            cvt_pack(v.z, v.w, h1, l1);
            int k2 = kq >> 1;
            Ah[k2*SA + row] = h0; Ah[(k2+1)*SA + row] = h1;
            Al[k2*SA + row] = l0; Al[(k2+1)*SA + row] = l1;
        }
        // stage B: 64x32 floats
#pragma unroll
        for (int u = 0; u < 2; u++) {
            int idx = tid + u*256;           // 0..511
            int row = idx >> 3, kq = (idx & 7) * 4;
            float4 v = *(const float4*)(W + (size_t)(n0+row)*MDIM + k0 + kq);
            unsigned h0, l0, h1, l1;
            cvt_pack(v.x, v.y, h0, l0);
            cvt_pack(v.z, v.w, h1, l1);
            int k2 = kq >> 1;
            Bh[k2*SB + row] = h0; Bh[(k2+1)*SB + row] = h1;
            Bl[k2*SB + row] = l0; Bl[(k2+1)*SB + row] = l1;
        }
        __syncthreads();

#pragma unroll
        for (int ks = 0; ks < 2; ks++) {
            const int k2o = ks * 8;
            unsigned ah[2][4], al[2][4], bh[4][2], bl[4][2];
#pragma unroll
            for (int mt = 0; mt < 2; mt++) {
                int m = warp_m*32 + mt*16 + group;
                ah[mt][0] = Ah[(k2o+tg)*SA + m];
                ah[mt][1] = Ah[(k2o+tg)*SA + m + 8];
                ah[mt][2] = Ah[(k2o+tg+4)*SA + m];
                ah[mt][3] = Ah[(k2o+tg+4)*SA + m + 8];
                al[mt][0] = Al[(k2o+tg)*SA + m];
                al[mt][1] = Al[(k2o+tg)*SA + m + 8];
                al[mt][2] = Al[(k2o+tg+4)*SA + m];
                al[mt][3] = Al[(k2o+tg+4)*SA + m + 8];
            }
#pragma unroll
            for (int nt = 0; nt < 4; nt++) {
                int n = warp_n*32 + nt*8 + group;
                bh[nt][0] = Bh[(k2o+tg)*SB + n];
                bh[nt][1] = Bh[(k2o+tg+4)*SB + n];
                bl[nt][0] = Bl[(k2o+tg)*SB + n];
                bl[nt][1] = Bl[(k2o+tg+4)*SB + n];
            }
#pragma unroll
            for (int mt = 0; mt < 2; mt++)
#pragma unroll
                for (int nt = 0; nt < 4; nt++) {
                    mma_bf16(acc[mt][nt], ah[mt], bh[nt]);
                    mma_bf16(acc[mt][nt], ah[mt], bl[nt]);
                    mma_bf16(acc[mt][nt], al[mt], bh[nt]);
                }
        }
    }

    // ---------------- fused layernorm epilogue (two 64-row halves) ----------
    const int s = n0 >> 10;
    const int h = (n0 & 1023) >> 6;
    float* et = (float*)smu;                 // [64][66] = 16896 B

    for (int rh = 0; rh < 2; rh++) {
        __syncthreads();
        if ((warp_m >> 1) == rh) {
#pragma unroll
            for (int mt = 0; mt < 2; mt++)
#pragma unroll
                for (int nt = 0; nt < 4; nt++) {
                    int r0 = warp_m*32 + mt*16 + group - rh*64;
                    int col = warp_n*32 + nt*8 + 2*tg;
                    *(float2*)&et[r0*66 + col] =
                        make_float2(acc[mt][nt][0], acc[mt][nt][1]);
                    *(float2*)&et[(r0+8)*66 + col] =
                        make_float2(acc[mt][nt][2], acc[mt][nt][3]);
                }
        }
        __syncthreads();
#pragma unroll
        for (int rr = 0; rr < 8; rr++) {
            int r  = warp*8 + rr;
            int gm = m0 + rh*64 + r;
            int bb = gm >> 11, n = gm & 2047;
            float v1 = et[r*66 + lane];
            float v2 = et[r*66 + lane + 32];
            size_t base = (((size_t)(bb*NHEADS + h))*SEQ + n)*HDIM;
            if (s == 2) {
                g_v[base + lane] = v1;
                g_v[base + lane + 32] = v2;
            } else {
                float sum = v1 + v2, sq = v1*v1 + v2*v2;
#pragma unroll
                for (int o = 16; o; o >>= 1) {
                    sum += __shfl_xor_sync(0xffffffffu, sum, o);
                    sq  += __shfl_xor_sync(0xffffffffu, sq,  o);
                }
                float mean = sum * (1.f/64.f);
                float var  = sq  * (1.f/64.f) - mean*mean;
                float rstd = rsqrtf(var + 1e-5f);
                if (s == 0) {
                    float y1 = ((v1-mean)*rstd*qw[lane]    + qb[lane])    * 0.125f;
                    float y2 = ((v2-mean)*rstd*qw[lane+32] + qb[lane+32]) * 0.125f;
                    g_q[base + lane] = y1;  g_q[base + lane + 32] = y2;
                } else {
                    float y1 = (v1-mean)*rstd*kw[lane]    + kb[lane];
                    float y2 = (v2-mean)*rstd*kw[lane+32] + kb[lane+32];
                    g_k[base + lane] = y1;  g_k[base + lane + 32] = y2;
                }
            }
        }
    }
}

// ---------------- kernel 3: output projection (bf16x3 mma) + bias -----------
__global__ __launch_bounds__(256, 2) void proj_gemm_kernel(
    const float* __restrict__ W, const float* __restrict__ bias,
    float* __restrict__ out)
{
    __shared__ unsigned smu[SM_U];
    unsigned* Ah = smu;
    unsigned* Al = Ah + 16*SA;
    unsigned* Bh = Al + 16*SA;
    unsigned* Bl = Bh + 16*SB;

    const int tid = threadIdx.x;
    const int m0 = blockIdx.y * 128;
    const int n0 = blockIdx.x * 64;
    const int warp = tid >> 5, lane = tid & 31;
    const int warp_m = warp >> 1, warp_n = warp & 1;
    const int group = lane >> 2, tg = lane & 3;

    float acc[2][4][4];
#pragma unroll
    for (int mt = 0; mt < 2; mt++)
#pragma unroll
        for (int nt = 0; nt < 4; nt++)
#pragma unroll
            for (int j = 0; j < 4; j++) acc[mt][nt][j] = 0.f;

    for (int k0 = 0; k0 < MDIM; k0 += 32) {
        __syncthreads();
#pragma unroll
        for (int u = 0; u < 4; u++) {
            int idx = tid + u*256;
            int row = idx >> 3, kq = (idx & 7) * 4;
            float4 v = *(const float4*)(g_ao + (size_t)(m0+row)*MDIM + k0 + kq);
            unsigned h0, l0, h1, l1;
            cvt_pack(v.x, v.y, h0, l0);
            cvt_pack(v.z, v.w, h1, l1);
            int k2 = kq >> 1;
            Ah[k2*SA + row] = h0; Ah[(k2+1)*SA + row] = h1;
            Al[k2*SA + row] = l0; Al[(k2+1)*SA + row] = l1;
        }
#pragma unroll
        for (int u = 0; u < 2; u++) {
            int idx = tid + u*256;
            int row = idx >> 3, kq = (idx & 7) * 4;
            float4 v = *(const float4*)(W + (size_t)(n0+row)*MDIM + k0 + kq);
            unsigned h0, l0, h1, l1;
            cvt_pack(v.x, v.y, h0, l0);
            cvt_pack(v.z, v.w, h1, l1);
            int k2 = kq >> 1;
            Bh[k2*SB + row] = h0; Bh[(k2+1)*SB + row] = h1;
            Bl[k2*SB + row] = l0; Bl[(k2+1)*SB + row] = l1;
        }
        __syncthreads();

#pragma unroll
        for (int ks = 0; ks < 2; ks++) {
            const int k2o = ks * 8;
            unsigned ah[2][4], al[2][4], bh[4][2], bl[4][2];
#pragma unroll
            for (int mt = 0; mt < 2; mt++) {
                int m = warp_m*32 + mt*16 + group;
                ah[mt][0] = Ah[(k2o+tg)*SA + m];
                ah[mt][1] = Ah[(k2o+tg)*SA + m + 8];
                ah[mt][2] = Ah[(k2o+tg+4)*SA + m];
                ah[mt][3] = Ah[(k2o+tg+4)*SA + m + 8];
                al[mt][0] = Al[(k2o+tg)*SA + m];
                al[mt][1] = Al[(k2o+tg)*SA + m + 8];
                al[mt][2] = Al[(k2o+tg+4)*SA + m];
                al[mt][3] = Al[(k2o+tg+4)*SA + m + 8];
            }
#pragma unroll
            for (int nt = 0; nt < 4; nt++) {
                int n = warp_n*32 + nt*8 + group;
                bh[nt][0] = Bh[(k2o+tg)*SB + n];
                bh[nt][1] = Bh[(k2o+tg+4)*SB + n];
                bl[nt][0] = Bl[(k2o+tg)*SB + n];
                bl[nt][1] = Bl[(k2o+tg+4)*SB + n];
            }
#pragma unroll
            for (int mt = 0; mt < 2; mt++)
#pragma unroll
                for (int nt = 0; nt < 4; nt++) {
                    mma_bf16(acc[mt][nt], ah[mt], bh[nt]);
                    mma_bf16(acc[mt][nt], ah[mt], bl[nt]);
                    mma_bf16(acc[mt][nt], al[mt], bh[nt]);
                }
        }
    }

    // bias + direct store
#pragma unroll
    for (int nt = 0; nt < 4; nt++) {
        int col = n0 + warp_n*32 + nt*8 + 2*tg;
        float b0 = bias[col], b1 = bias[col+1];
#pragma unroll
        for (int mt = 0; mt < 2; mt++) {
            int row = m0 + warp_m*32 + mt*16 + group;
            *(float2*)(out + (size_t)row*MDIM + col) =
                make_float2(acc[mt][nt][0] + b0, acc[mt][nt][1] + b1);
            *(float2*)(out + (size_t)(row+8)*MDIM + col) =
                make_float2(acc[mt][nt][2] + b0, acc[mt][nt][3] + b1);
        }
    }
}

// ---------------- kernel 2: flash attention (unchanged scalar fp32) ---------
__global__ __launch_bounds__(256) void flash_attn_kernel(const void* __restrict__ maskp)
{
    extern __shared__ float fsm[];
    float* qs  = fsm;            // [64 row][64 d]
    float* kst = fsm + 4096;     // [64 d][64 key], XOR-swizzled
    float* vs  = fsm + 8192;     // [64 key][64 d]
    float* ps  = fsm + 12288;    // [64 row][64 col]
    const int tid = threadIdx.x;
    const int q0 = blockIdx.x * 64;
    const int h  = blockIdx.y;
    const int b  = blockIdx.z;
    const size_t bh = (size_t)(b*NHEADS + h) * SEQ * HDIM;
    const float* Q = g_q + bh;
    const float* K = g_k + bh;
    const float* V = g_v + bh;
    const int ty = tid >> 4, tx = tid & 15;

#pragma unroll
    for (int u = 0; u < 4; u++) {
        int f = tid + u*256;
        int row = f >> 4, d = (f & 15) * 4;
        *(float4*)(qs + row*64 + d) = *(const float4*)(Q + (size_t)(q0+row)*HDIM + d);
    }

    float m[4], l[4], o[4][4];
#pragma unroll
    for (int i = 0; i < 4; i++) {
        m[i] = -INFINITY; l[i] = 0.f;
#pragma unroll
        for (int j = 0; j < 4; j++) o[i][j] = 0.f;
    }
    const int kind = g_mask_kind;
    const int*           mi = (const int*)maskp;
    const unsigned char* mb = (const unsigned char*)maskp;
    const float*         mf = (const float*)maskp;
    const size_t mbase0 = (size_t)b * SEQ * SEQ;

    for (int kt = 0; kt < SEQ/64; kt++) {
        __syncthreads();
#pragma unroll
        for (int u = 0; u < 4; u++) {
            int f = tid + u*256;
            int key = f >> 4, d = (f & 15) * 4;
            float4 kv = *(const float4*)(K + (size_t)(kt*64+key)*HDIM + d);
            int sk = key ^ d;
            kst[(d+0)*64 + sk] = kv.x;
            kst[(d+1)*64 + sk] = kv.y;
            kst[(d+2)*64 + sk] = kv.z;
            kst[(d+3)*64 + sk] = kv.w;
            *(float4*)(vs + key*64 + d) = *(const float4*)(V + (size_t)(kt*64+key)*HDIM + d);
        }
        __syncthreads();

        float s[4][4];
#pragma unroll
        for (int i = 0; i < 4; i++)
#pragma unroll
            for (int j = 0; j < 4; j++) s[i][j] = 0.f;

#pragma unroll
        for (int d = 0; d < 64; d += 4) {
            float a4[4][4], k4[4][4];
#pragma unroll
            for (int i = 0; i < 4; i++)
                *(float4*)a4[i] = *(const float4*)(qs + (ty*4+i)*64 + d);
#pragma unroll
            for (int dd = 0; dd < 4; dd++)
                *(float4*)k4[dd] = *(const float4*)(kst + (d+dd)*64 + ((tx*4) ^ d));
#pragma unroll
            for (int i = 0; i < 4; i++)
#pragma unroll
                for (int dd = 0; dd < 4; dd++)
#pragma unroll
                    for (int j = 0; j < 4; j++)
                        s[i][j] = fmaf(a4[i][dd], k4[dd][j], s[i][j]);
        }

#pragma unroll
        for (int i = 0; i < 4; i++) {
            int qr = q0 + ty*4 + i;
            size_t midx = mbase0 + (size_t)qr*SEQ + (size_t)kt*64 + tx*4;
            bool mk[4];
            if (kind == 0)      { for (int j = 0; j < 4; j++) mk[j] = mi[midx+j] != 0; }
            else if (kind == 1) { for (int j = 0; j < 4; j++) mk[j] = mb[midx+j] != 0; }
            else                { for (int j = 0; j < 4; j++) mk[j] = mf[midx+j] != 0.f; }
#pragma unroll
            for (int j = 0; j < 4; j++) if (mk[j]) s[i][j] = -1e30f;

            float tmax = fmaxf(fmaxf(s[i][0], s[i][1]), fmaxf(s[i][2], s[i][3]));
#pragma unroll
            for (int off = 8; off; off >>= 1)
                tmax = fmaxf(tmax, __shfl_xor_sync(0xffffffffu, tmax, off));
            float mn   = fmaxf(m[i], tmax);
            float corr = __expf(m[i] - mn);
            m[i] = mn;
            float ts = 0.f;
#pragma unroll
            for (int j = 0; j < 4; j++) {
                float p = mk[j] ? 0.f : __expf(s[i][j] - mn);
                s[i][j] = p; ts += p;
            }
#pragma unroll
            for (int off = 8; off; off >>= 1)
                ts += __shfl_xor_sync(0xffffffffu, ts, off);
            l[i] = l[i]*corr + ts;
#pragma unroll
            for (int j = 0; j < 4; j++) o[i][j] *= corr;
            *(float4*)(ps + (ty*4+i)*64 + tx*4) =
                make_float4(s[i][0], s[i][1], s[i][2], s[i][3]);
        }
        __syncthreads();

#pragma unroll
        for (int jk = 0; jk < 64; jk += 4) {
            float p4[4][4], v4[4][4];
#pragma unroll
            for (int i = 0; i < 4; i++)
                *(float4*)p4[i] = *(const float4*)(ps + (ty*4+i)*64 + jk);
#pragma unroll
            for (int jj = 0; jj < 4; jj++)
                *(float4*)v4[jj] = *(const float4*)(vs + (jk+jj)*64 + tx*4);
#pragma unroll
            for (int i = 0; i < 4; i++)
#pragma unroll
                for (int jj = 0; jj < 4; jj++)
#pragma unroll
                    for (int j = 0; j < 4; j++)
                        o[i][j] = fmaf(p4[i][jj], v4[jj][j], o[i][j]);
        }
    }

#pragma unroll
    for (int i = 0; i < 4; i++) {
        float inv = 1.f / l[i];
        float4 ov = make_float4(o[i][0]*inv, o[i][1]*inv, o[i][2]*inv, o[i][3]*inv);
        size_t oi = ((size_t)b*SEQ + q0 + ty*4 + i)*MDIM + h*HDIM + tx*4;
        *(float4*)(g_ao + oi) = ov;
    }
}

// ---------------- launch ----------------------------------------------------
extern "C" void kernel_launch(void* const* d_in, const int* in_sizes, int n_in,
                              void* d_out, int out_size)
{
    const float* x      = (const float*)d_in[0];
    const void*  mask   = d_in[1];
    const float* qkv_w  = (const float*)d_in[2];
    const float* q_nw   = (const float*)d_in[3];
    const float* q_nb   = (const float*)d_in[4];
    const float* k_nw   = (const float*)d_in[5];
    const float* k_nb   = (const float*)d_in[6];
    const float* proj_w = (const float*)d_in[7];
    const float* proj_b = (const float*)d_in[8];
    float* out = (float*)d_out;

    probe_mask_kernel<<<1, 256>>>((const unsigned int*)mask);

    qkv_gemm_ln_kernel<<<dim3(48, 32), 256>>>(x, qkv_w, q_nw, q_nb, k_nw, k_nb);

    cudaFuncSetAttribute(flash_attn_kernel,
                         cudaFuncAttributeMaxDynamicSharedMemorySize, 65536);
    flash_attn_kernel<<<dim3(32, NHEADS, BATCH), 256, 65536>>>(mask);

    proj_gemm_kernel<<<dim3(16, 32), 256>>>(proj_w, proj_b, out);
}

// round 4
// speedup vs baseline: 1.6591x; 1.3083x over previous
#include <cuda_runtime.h>
#include <cuda_bf16.h>
#include <math.h>

#define SEQ   2048
#define BATCH 2
#define NHEADS 16
#define HDIM  64
#define MDIM  1024
#define TOKENS (BATCH*SEQ)   // 4096

// ---------------- scratch (device globals: no allocations allowed) ----------
__device__ float g_q[BATCH*NHEADS*SEQ*HDIM];   // (B,H,N,D), LN'd + scaled
__device__ float g_k[BATCH*NHEADS*SEQ*HDIM];   // (B,H,N,D), LN'd
__device__ float g_v[BATCH*NHEADS*SEQ*HDIM];   // (B,H,N,D)
__device__ float g_ao[(size_t)TOKENS*MDIM];    // (B,N,C) attention output
__device__ int   g_mask_kind;                  // 0=int32, 1=uint8, 2=float32

// ---------------- helpers ----------------------------------------------------
__device__ __forceinline__ void cvt_pack(float x0, float x1, unsigned &h, unsigned &l)
{
    __nv_bfloat16 h0 = __float2bfloat16_rn(x0);
    __nv_bfloat16 h1 = __float2bfloat16_rn(x1);
    __nv_bfloat16 l0 = __float2bfloat16_rn(x0 - __bfloat162float(h0));
    __nv_bfloat16 l1 = __float2bfloat16_rn(x1 - __bfloat162float(h1));
    __nv_bfloat162 hp; hp.x = h0; hp.y = h1;
    __nv_bfloat162 lp; lp.x = l0; lp.y = l1;
    h = *reinterpret_cast<unsigned*>(&hp);
    l = *reinterpret_cast<unsigned*>(&lp);
}

__device__ __forceinline__ void mma_bf16(float* c, const unsigned* a, const unsigned* b)
{
    asm volatile(
        "mma.sync.aligned.m16n8k16.row.col.f32.bf16.bf16.f32 "
        "{%0,%1,%2,%3},{%4,%5,%6,%7},{%8,%9},{%0,%1,%2,%3};"
        : "+f"(c[0]), "+f"(c[1]), "+f"(c[2]), "+f"(c[3])
        : "r"(a[0]), "r"(a[1]), "r"(a[2]), "r"(a[3]), "r"(b[0]), "r"(b[1]));
}

#define SA 132
#define SB 68
#define SM_U (2*16*SA + 2*16*SB)

// ---------------- mask dtype probe ------------------------------------------
__global__ void probe_mask_kernel(const unsigned int* __restrict__ m)
{
    __shared__ int s_ni, s_nf;
    if (threadIdx.x == 0) { s_ni = 0; s_nf = 0; }
    __syncthreads();
    int ni = 0, nf = 0;
    for (int i = threadIdx.x; i < 4096; i += 256) {
        unsigned w = m[i];
        if (w > 1u) ni = 1;
        if (w != 0u && w != 0x3F800000u) nf = 1;
    }
    if (ni) atomicOr(&s_ni, 1);
    if (nf) atomicOr(&s_nf, 1);
    __syncthreads();
    if (threadIdx.x == 0)
        g_mask_kind = (s_ni == 0) ? 0 : (s_nf == 0) ? 2 : 1;
}

// ---------------- kernel 1: QKV GEMM (bf16x3 mma) + fused layernorm ---------
__global__ __launch_bounds__(256, 2) void qkv_gemm_ln_kernel(
    const float* __restrict__ X, const float* __restrict__ W,
    const float* __restrict__ qw, const float* __restrict__ qb,
    const float* __restrict__ kw, const float* __restrict__ kb)
{
    __shared__ unsigned smu[SM_U];
    unsigned* Ah = smu;
    unsigned* Al = Ah + 16*SA;
    unsigned* Bh = Al + 16*SA;
    unsigned* Bl = Bh + 16*SB;

    const int tid = threadIdx.x;
    const int m0 = blockIdx.y * 128;
    const int n0 = blockIdx.x * 64;
    const int warp = tid >> 5, lane = tid & 31;
    const int warp_m = warp >> 1, warp_n = warp & 1;
    const int group = lane >> 2, tg = lane & 3;

    float acc[2][4][4];
#pragma unroll
    for (int mt = 0; mt < 2; mt++)
#pragma unroll
        for (int nt = 0; nt < 4; nt++)
#pragma unroll
            for (int j = 0; j < 4; j++) acc[mt][nt][j] = 0.f;

    for (int k0 = 0; k0 < MDIM; k0 += 32) {
        __syncthreads();
#pragma unroll
        for (int u = 0; u < 4; u++) {
            int idx = tid + u*256;
            int row = idx >> 3, kq = (idx & 7) * 4;
            float4 v = *(const float4*)(X + (size_t)(m0+row)*MDIM + k0 + kq);
            unsigned h0, l0, h1, l1;
            cvt_pack(v.x, v.y, h0, l0);
            cvt_pack(v.z, v.w, h1, l1);
            int k2 = kq >> 1;
            Ah[k2*SA + row] = h0; Ah[(k2+1)*SA + row] = h1;
            Al[k2*SA + row] = l0; Al[(k2+1)*SA + row] = l1;
        }
#pragma unroll
        for (int u = 0; u < 2; u++) {
            int idx = tid + u*256;
            int row = idx >> 3, kq = (idx & 7) * 4;
            float4 v = *(const float4*)(W + (size_t)(n0+row)*MDIM + k0 + kq);
            unsigned h0, l0, h1, l1;
            cvt_pack(v.x, v.y, h0, l0);
            cvt_pack(v.z, v.w, h1, l1);
            int k2 = kq >> 1;
            Bh[k2*SB + row] = h0; Bh[(k2+1)*SB + row] = h1;
            Bl[k2*SB + row] = l0; Bl[(k2+1)*SB + row] = l1;
        }
        __syncthreads();

#pragma unroll
        for (int ks = 0; ks < 2; ks++) {
            const int k2o = ks * 8;
            unsigned ah[2][4], al[2][4], bh[4][2], bl[4][2];
#pragma unroll
            for (int mt = 0; mt < 2; mt++) {
                int m = warp_m*32 + mt*16 + group;
                ah[mt][0] = Ah[(k2o+tg)*SA + m];
                ah[mt][1] = Ah[(k2o+tg)*SA + m + 8];
                ah[mt][2] = Ah[(k2o+tg+4)*SA + m];
                ah[mt][3] = Ah[(k2o+tg+4)*SA + m + 8];
                al[mt][0] = Al[(k2o+tg)*SA + m];
                al[mt][1] = Al[(k2o+tg)*SA + m + 8];
                al[mt][2] = Al[(k2o+tg+4)*SA + m];
                al[mt][3] = Al[(k2o+tg+4)*SA + m + 8];
            }
#pragma unroll
            for (int nt = 0; nt < 4; nt++) {
                int n = warp_n*32 + nt*8 + group;
                bh[nt][0] = Bh[(k2o+tg)*SB + n];
                bh[nt][1] = Bh[(k2o+tg+4)*SB + n];
                bl[nt][0] = Bl[(k2o+tg)*SB + n];
                bl[nt][1] = Bl[(k2o+tg+4)*SB + n];
            }
#pragma unroll
            for (int mt = 0; mt < 2; mt++)
#pragma unroll
                for (int nt = 0; nt < 4; nt++) {
                    mma_bf16(acc[mt][nt], ah[mt], bh[nt]);
                    mma_bf16(acc[mt][nt], ah[mt], bl[nt]);
                    mma_bf16(acc[mt][nt], al[mt], bh[nt]);
                }
        }
    }

    const int s = n0 >> 10;
    const int h = (n0 & 1023) >> 6;
    float* et = (float*)smu;

    for (int rh = 0; rh < 2; rh++) {
        __syncthreads();
        if ((warp_m >> 1) == rh) {
#pragma unroll
            for (int mt = 0; mt < 2; mt++)
#pragma unroll
                for (int nt = 0; nt < 4; nt++) {
                    int r0 = warp_m*32 + mt*16 + group - rh*64;
                    int col = warp_n*32 + nt*8 + 2*tg;
                    *(float2*)&et[r0*66 + col] =
                        make_float2(acc[mt][nt][0], acc[mt][nt][1]);
                    *(float2*)&et[(r0+8)*66 + col] =
                        make_float2(acc[mt][nt][2], acc[mt][nt][3]);
                }
        }
        __syncthreads();
#pragma unroll
        for (int rr = 0; rr < 8; rr++) {
            int r  = warp*8 + rr;
            int gm = m0 + rh*64 + r;
            int bb = gm >> 11, n = gm & 2047;
            float v1 = et[r*66 + lane];
            float v2 = et[r*66 + lane + 32];
            size_t base = (((size_t)(bb*NHEADS + h))*SEQ + n)*HDIM;
            if (s == 2) {
                g_v[base + lane] = v1;
                g_v[base + lane + 32] = v2;
            } else {
                float sum = v1 + v2, sq = v1*v1 + v2*v2;
#pragma unroll
                for (int o = 16; o; o >>= 1) {
                    sum += __shfl_xor_sync(0xffffffffu, sum, o);
                    sq  += __shfl_xor_sync(0xffffffffu, sq,  o);
                }
                float mean = sum * (1.f/64.f);
                float var  = sq  * (1.f/64.f) - mean*mean;
                float rstd = rsqrtf(var + 1e-5f);
                if (s == 0) {
                    float y1 = ((v1-mean)*rstd*qw[lane]    + qb[lane])    * 0.125f;
                    float y2 = ((v2-mean)*rstd*qw[lane+32] + qb[lane+32]) * 0.125f;
                    g_q[base + lane] = y1;  g_q[base + lane + 32] = y2;
                } else {
                    float y1 = (v1-mean)*rstd*kw[lane]    + kb[lane];
                    float y2 = (v2-mean)*rstd*kw[lane+32] + kb[lane+32];
                    g_k[base + lane] = y1;  g_k[base + lane + 32] = y2;
                }
            }
        }
    }
}

// ---------------- kernel 3: output projection (bf16x3 mma) + bias -----------
__global__ __launch_bounds__(256, 2) void proj_gemm_kernel(
    const float* __restrict__ W, const float* __restrict__ bias,
    float* __restrict__ out)
{
    __shared__ unsigned smu[SM_U];
    unsigned* Ah = smu;
    unsigned* Al = Ah + 16*SA;
    unsigned* Bh = Al + 16*SA;
    unsigned* Bl = Bh + 16*SB;

    const int tid = threadIdx.x;
    const int m0 = blockIdx.y * 128;
    const int n0 = blockIdx.x * 64;
    const int warp = tid >> 5, lane = tid & 31;
    const int warp_m = warp >> 1, warp_n = warp & 1;
    const int group = lane >> 2, tg = lane & 3;

    float acc[2][4][4];
#pragma unroll
    for (int mt = 0; mt < 2; mt++)
#pragma unroll
        for (int nt = 0; nt < 4; nt++)
#pragma unroll
            for (int j = 0; j < 4; j++) acc[mt][nt][j] = 0.f;

    for (int k0 = 0; k0 < MDIM; k0 += 32) {
        __syncthreads();
#pragma unroll
        for (int u = 0; u < 4; u++) {
            int idx = tid + u*256;
            int row = idx >> 3, kq = (idx & 7) * 4;
            float4 v = *(const float4*)(g_ao + (size_t)(m0+row)*MDIM + k0 + kq);
            unsigned h0, l0, h1, l1;
            cvt_pack(v.x, v.y, h0, l0);
            cvt_pack(v.z, v.w, h1, l1);
            int k2 = kq >> 1;
            Ah[k2*SA + row] = h0; Ah[(k2+1)*SA + row] = h1;
            Al[k2*SA + row] = l0; Al[(k2+1)*SA + row] = l1;
        }
#pragma unroll
        for (int u = 0; u < 2; u++) {
            int idx = tid + u*256;
            int row = idx >> 3, kq = (idx & 7) * 4;
            float4 v = *(const float4*)(W + (size_t)(n0+row)*MDIM + k0 + kq);
            unsigned h0, l0, h1, l1;
            cvt_pack(v.x, v.y, h0, l0);
            cvt_pack(v.z, v.w, h1, l1);
            int k2 = kq >> 1;
            Bh[k2*SB + row] = h0; Bh[(k2+1)*SB + row] = h1;
            Bl[k2*SB + row] = l0; Bl[(k2+1)*SB + row] = l1;
        }
        __syncthreads();

#pragma unroll
        for (int ks = 0; ks < 2; ks++) {
            const int k2o = ks * 8;
            unsigned ah[2][4], al[2][4], bh[4][2], bl[4][2];
#pragma unroll
            for (int mt = 0; mt < 2; mt++) {
                int m = warp_m*32 + mt*16 + group;
                ah[mt][0] = Ah[(k2o+tg)*SA + m];
                ah[mt][1] = Ah[(k2o+tg)*SA + m + 8];
                ah[mt][2] = Ah[(k2o+tg+4)*SA + m];
                ah[mt][3] = Ah[(k2o+tg+4)*SA + m + 8];
                al[mt][0] = Al[(k2o+tg)*SA + m];
                al[mt][1] = Al[(k2o+tg)*SA + m + 8];
                al[mt][2] = Al[(k2o+tg+4)*SA + m];
                al[mt][3] = Al[(k2o+tg+4)*SA + m + 8];
            }
#pragma unroll
            for (int nt = 0; nt < 4; nt++) {
                int n = warp_n*32 + nt*8 + group;
                bh[nt][0] = Bh[(k2o+tg)*SB + n];
                bh[nt][1] = Bh[(k2o+tg+4)*SB + n];
                bl[nt][0] = Bl[(k2o+tg)*SB + n];
                bl[nt][1] = Bl[(k2o+tg+4)*SB + n];
            }
#pragma unroll
            for (int mt = 0; mt < 2; mt++)
#pragma unroll
                for (int nt = 0; nt < 4; nt++) {
                    mma_bf16(acc[mt][nt], ah[mt], bh[nt]);
                    mma_bf16(acc[mt][nt], ah[mt], bl[nt]);
                    mma_bf16(acc[mt][nt], al[mt], bh[nt]);
                }
        }
    }

#pragma unroll
    for (int nt = 0; nt < 4; nt++) {
        int col = n0 + warp_n*32 + nt*8 + 2*tg;
        float b0 = bias[col], b1 = bias[col+1];
#pragma unroll
        for (int mt = 0; mt < 2; mt++) {
            int row = m0 + warp_m*32 + mt*16 + group;
            *(float2*)(out + (size_t)row*MDIM + col) =
                make_float2(acc[mt][nt][0] + b0, acc[mt][nt][1] + b1);
            *(float2*)(out + (size_t)(row+8)*MDIM + col) =
                make_float2(acc[mt][nt][2] + b0, acc[mt][nt][3] + b1);
        }
    }
}

// ---------------- kernel 2: flash attention via bf16x3 mma -------------------
// CTA: 256 thr / 8 warps; 128 queries of one (b,h); warp owns 16 query rows.
// Key tiles of 64; K/V staged to smem as bf16 hi/lo in k2-major conflict-free
// layout; mask compressed to 1 bit/entry in smem; P fed to PV mma directly
// from QK accumulator fragments (identical layout).
#define MASKED (-2e30f)
#define MINIT  (-1e30f)

__global__ __launch_bounds__(256) void flash_attn_mma_kernel(const void* __restrict__ maskp)
{
    __shared__ unsigned Kh[32*68], Kl[32*68], Vh[32*68], Vl[32*68];
    __shared__ unsigned msk[256];        // [128 rows][2 words]

    const int tid = threadIdx.x;
    const int warp = tid >> 5, lane = tid & 31;
    const int group = lane >> 2, tg = lane & 3;
    const int q0 = blockIdx.x * 128;
    const int h  = blockIdx.y;
    const int b  = blockIdx.z;
    const size_t bh = (size_t)(b*NHEADS + h) * SEQ * HDIM;
    const float* Q = g_q + bh;
    const float* K = g_k + bh;
    const float* V = g_v + bh;
    const int kind = g_mask_kind;

    // ---- Q fragments (persistent, bf16 hi/lo), rows row0, row0+8 ----
    const int row0 = q0 + warp*16 + group;
    unsigned qh[4][4], ql[4][4];
#pragma unroll
    for (int ks = 0; ks < 4; ks++) {
        float2 e0 = *(const float2*)(Q + (size_t)row0*HDIM     + ks*16 + 2*tg);
        float2 e1 = *(const float2*)(Q + (size_t)(row0+8)*HDIM + ks*16 + 2*tg);
        float2 e2 = *(const float2*)(Q + (size_t)row0*HDIM     + ks*16 + 8 + 2*tg);
        float2 e3 = *(const float2*)(Q + (size_t)(row0+8)*HDIM + ks*16 + 8 + 2*tg);
        cvt_pack(e0.x, e0.y, qh[ks][0], ql[ks][0]);
        cvt_pack(e1.x, e1.y, qh[ks][1], ql[ks][1]);
        cvt_pack(e2.x, e2.y, qh[ks][2], ql[ks][2]);
        cvt_pack(e3.x, e3.y, qh[ks][3], ql[ks][3]);
    }

    float m0r = MINIT, m1r = MINIT, l0r = 0.f, l1r = 0.f;
    float o[8][4];
#pragma unroll
    for (int nt = 0; nt < 8; nt++)
#pragma unroll
        for (int j = 0; j < 4; j++) o[nt][j] = 0.f;

    for (int kt = 0; kt < SEQ/64; kt++) {
        __syncthreads();
        // ---- stage K tile: [64 keys][64 d] -> Kh/Kl[k2=d/2][key] ----
#pragma unroll
        for (int u = 0; u < 4; u++) {
            int idx = tid + u*256;
            int key = idx >> 4, dq = (idx & 15) * 4;
            float4 kv = *(const float4*)(K + (size_t)(kt*64+key)*HDIM + dq);
            unsigned h0, lo0, h1, lo1;
            cvt_pack(kv.x, kv.y, h0, lo0);
            cvt_pack(kv.z, kv.w, h1, lo1);
            int k2 = dq >> 1;
            Kh[k2*68 + key] = h0; Kh[(k2+1)*68 + key] = h1;
            Kl[k2*68 + key] = lo0; Kl[(k2+1)*68 + key] = lo1;
        }
        // ---- stage V tile: [64 keys][64 d] -> Vh/Vl[k2=key/2][d] ----
#pragma unroll
        for (int u = 0; u < 2; u++) {
            int idx = tid + u*256;
            int k2 = idx >> 4, dq = (idx & 15) * 4;
            float4 va = *(const float4*)(V + (size_t)(kt*64 + 2*k2)*HDIM + dq);
            float4 vb = *(const float4*)(V + (size_t)(kt*64 + 2*k2 + 1)*HDIM + dq);
            unsigned hh, ll;
            cvt_pack(va.x, vb.x, hh, ll); Vh[k2*68 + dq    ] = hh; Vl[k2*68 + dq    ] = ll;
            cvt_pack(va.y, vb.y, hh, ll); Vh[k2*68 + dq + 1] = hh; Vl[k2*68 + dq + 1] = ll;
            cvt_pack(va.z, vb.z, hh, ll); Vh[k2*68 + dq + 2] = hh; Vl[k2*68 + dq + 2] = ll;
            cvt_pack(va.w, vb.w, hh, ll); Vh[k2*68 + dq + 3] = hh; Vl[k2*68 + dq + 3] = ll;
        }
        // ---- stage mask bits: row r, keys [kt*64, kt*64+64) -> 2 words ----
        {
            int r = tid >> 1, hf = tid & 1;
            size_t off = (size_t)b*SEQ*SEQ + (size_t)(q0+r)*SEQ + kt*64 + hf*32;
            unsigned bits = 0;
            if (kind == 1) {
                const uchar4* p = (const uchar4*)((const unsigned char*)maskp + off);
#pragma unroll
                for (int i = 0; i < 8; i++) {
                    uchar4 u4 = p[i];
                    bits |= (u4.x ? 1u : 0u) << (i*4);
                    bits |= (u4.y ? 1u : 0u) << (i*4+1);
                    bits |= (u4.z ? 1u : 0u) << (i*4+2);
                    bits |= (u4.w ? 1u : 0u) << (i*4+3);
                }
            } else {
                const uint4* p = (const uint4*)((const unsigned*)maskp + off);
#pragma unroll
                for (int i = 0; i < 8; i++) {
                    uint4 u4 = p[i];
                    bits |= (u4.x ? 1u : 0u) << (i*4);
                    bits |= (u4.y ? 1u : 0u) << (i*4+1);
                    bits |= (u4.z ? 1u : 0u) << (i*4+2);
                    bits |= (u4.w ? 1u : 0u) << (i*4+3);
                }
            }
            msk[r*2 + hf] = bits;
        }
        __syncthreads();

        // ---- S = Q K^T for this tile (bf16x3) ----
        float s[8][4];
#pragma unroll
        for (int nt = 0; nt < 8; nt++)
#pragma unroll
            for (int j = 0; j < 4; j++) s[nt][j] = 0.f;
#pragma unroll
        for (int nt = 0; nt < 8; nt++) {
            int n = nt*8 + group;
#pragma unroll
            for (int ks = 0; ks < 4; ks++) {
                unsigned bhf[2], blf[2];
                bhf[0] = Kh[(ks*8+tg)*68 + n];
                bhf[1] = Kh[(ks*8+tg+4)*68 + n];
                blf[0] = Kl[(ks*8+tg)*68 + n];
                blf[1] = Kl[(ks*8+tg+4)*68 + n];
                mma_bf16(s[nt], qh[ks], bhf);
                mma_bf16(s[nt], qh[ks], blf);
                mma_bf16(s[nt], ql[ks], bhf);
            }
        }

        // ---- mask + online softmax ----
        int lr = warp*16 + group;
        unsigned w0lo = msk[lr*2],       w0hi = msk[lr*2 + 1];
        unsigned w1lo = msk[(lr+8)*2],   w1hi = msk[(lr+8)*2 + 1];
        float rm0 = MINIT, rm1 = MINIT;
#pragma unroll
        for (int nt = 0; nt < 8; nt++) {
            int kidx = nt*8 + 2*tg;
            unsigned wr0 = (nt < 4) ? w0lo : w0hi;
            unsigned wr1 = (nt < 4) ? w1lo : w1hi;
            int sh = kidx & 31;
            if ((wr0 >> sh) & 1)       s[nt][0] = MASKED;
            if ((wr0 >> (sh+1)) & 1)   s[nt][1] = MASKED;
            if ((wr1 >> sh) & 1)       s[nt][2] = MASKED;
            if ((wr1 >> (sh+1)) & 1)   s[nt][3] = MASKED;
            rm0 = fmaxf(rm0, fmaxf(s[nt][0], s[nt][1]));
            rm1 = fmaxf(rm1, fmaxf(s[nt][2], s[nt][3]));
        }
        rm0 = fmaxf(rm0, __shfl_xor_sync(0xffffffffu, rm0, 1));
        rm0 = fmaxf(rm0, __shfl_xor_sync(0xffffffffu, rm0, 2));
        rm1 = fmaxf(rm1, __shfl_xor_sync(0xffffffffu, rm1, 1));
        rm1 = fmaxf(rm1, __shfl_xor_sync(0xffffffffu, rm1, 2));
        float mn0 = fmaxf(m0r, rm0), mn1 = fmaxf(m1r, rm1);
        float c0 = __expf(m0r - mn0), c1 = __expf(m1r - mn1);
        m0r = mn0; m1r = mn1;

        float ls0 = 0.f, ls1 = 0.f;
#pragma unroll
        for (int nt = 0; nt < 8; nt++) {
            s[nt][0] = __expf(s[nt][0] - mn0);
            s[nt][1] = __expf(s[nt][1] - mn0);
            s[nt][2] = __expf(s[nt][2] - mn1);
            s[nt][3] = __expf(s[nt][3] - mn1);
            ls0 += s[nt][0] + s[nt][1];
            ls1 += s[nt][2] + s[nt][3];
        }
        ls0 += __shfl_xor_sync(0xffffffffu, ls0, 1);
        ls0 += __shfl_xor_sync(0xffffffffu, ls0, 2);
        ls1 += __shfl_xor_sync(0xffffffffu, ls1, 1);
        ls1 += __shfl_xor_sync(0xffffffffu, ls1, 2);
        l0r = l0r*c0 + ls0;
        l1r = l1r*c1 + ls1;
#pragma unroll
        for (int nt = 0; nt < 8; nt++) {
            o[nt][0] *= c0; o[nt][1] *= c0;
            o[nt][2] *= c1; o[nt][3] *= c1;
        }

        // ---- O += P V (bf16x3); P frags come straight from s accumulators --
#pragma unroll
        for (int j = 0; j < 4; j++) {      // kstep over keys 16j..16j+15
            unsigned ph[4], pl[4];
            cvt_pack(s[2*j][0],   s[2*j][1],   ph[0], pl[0]);
            cvt_pack(s[2*j][2],   s[2*j][3],   ph[1], pl[1]);
            cvt_pack(s[2*j+1][0], s[2*j+1][1], ph[2], pl[2]);
            cvt_pack(s[2*j+1][2], s[2*j+1][3], ph[3], pl[3]);
#pragma unroll
            for (int nt = 0; nt < 8; nt++) {
                int n = nt*8 + group;
                unsigned vhf[2], vlf[2];
                vhf[0] = Vh[(j*8+tg)*68 + n];
                vhf[1] = Vh[(j*8+tg+4)*68 + n];
                vlf[0] = Vl[(j*8+tg)*68 + n];
                vlf[1] = Vl[(j*8+tg+4)*68 + n];
                mma_bf16(o[nt], ph, vhf);
                mma_bf16(o[nt], ph, vlf);
                mma_bf16(o[nt], pl, vhf);
            }
        }
    }

    // ---- finalize + store to g_ao ----
    float inv0 = 1.f / l0r, inv1 = 1.f / l1r;
#pragma unroll
    for (int nt = 0; nt < 8; nt++) {
        int col = h*HDIM + nt*8 + 2*tg;
        *(float2*)(g_ao + ((size_t)(b*SEQ) + row0)*MDIM + col) =
            make_float2(o[nt][0]*inv0, o[nt][1]*inv0);
        *(float2*)(g_ao + ((size_t)(b*SEQ) + row0 + 8)*MDIM + col) =
            make_float2(o[nt][2]*inv1, o[nt][3]*inv1);
    }
}

// ---------------- launch ----------------------------------------------------
extern "C" void kernel_launch(void* const* d_in, const int* in_sizes, int n_in,
                              void* d_out, int out_size)
{
    const float* x      = (const float*)d_in[0];
    const void*  mask   = d_in[1];
    const float* qkv_w  = (const float*)d_in[2];
    const float* q_nw   = (const float*)d_in[3];
    const float* q_nb   = (const float*)d_in[4];
    const float* k_nw   = (const float*)d_in[5];
    const float* k_nb   = (const float*)d_in[6];
    const float* proj_w = (const float*)d_in[7];
    const float* proj_b = (const float*)d_in[8];
    float* out = (float*)d_out;

    probe_mask_kernel<<<1, 256>>>((const unsigned int*)mask);

    qkv_gemm_ln_kernel<<<dim3(48, 32), 256>>>(x, qkv_w, q_nw, q_nb, k_nw, k_nb);

    flash_attn_mma_kernel<<<dim3(16, NHEADS, BATCH), 256>>>(mask);

    proj_gemm_kernel<<<dim3(16, 32), 256>>>(proj_w, proj_b, out);
}

// round 6
// speedup vs baseline: 2.4280x; 1.4634x over previous
#include <cuda_runtime.h>
#include <cuda_bf16.h>
#include <math.h>

#define SEQ   2048
#define BATCH 2
#define NHEADS 16
#define HDIM  64
#define MDIM  1024

#define MASKED (-2e30f)
#define MINIT  (-1e30f)

// ---------------- scratch (device globals; no allocations allowed) ----------
__device__ __align__(16) unsigned g_Xh[4096*512],  g_Xl[4096*512];    // X bf16 hi/lo
__device__ __align__(16) unsigned g_Wqh[3072*512], g_Wql[3072*512];   // qkv_w
__device__ __align__(16) unsigned g_Pwh[1024*512], g_Pwl[1024*512];   // proj_w
__device__ __align__(16) unsigned g_qh[65536*32],  g_ql[65536*32];    // (b,h,n) rows of 64 d
__device__ __align__(16) unsigned g_kh[65536*32],  g_kl[65536*32];
__device__ __align__(16) unsigned g_vh[65536*32],  g_vl[65536*32];
__device__ __align__(16) unsigned g_aoh[4096*512], g_aol[4096*512];   // attn out bf16 hi/lo
__device__ unsigned g_mb[4096*64];                                    // mask bits
__device__ int g_mask_kind;                                           // 0/2=word, 1=byte

// ---------------- helpers ----------------------------------------------------
__device__ __forceinline__ void cvt_pack(float x0, float x1, unsigned &h, unsigned &l)
{
    __nv_bfloat16 h0 = __float2bfloat16_rn(x0);
    __nv_bfloat16 h1 = __float2bfloat16_rn(x1);
    __nv_bfloat16 l0 = __float2bfloat16_rn(x0 - __bfloat162float(h0));
    __nv_bfloat16 l1 = __float2bfloat16_rn(x1 - __bfloat162float(h1));
    __nv_bfloat162 hp; hp.x = h0; hp.y = h1;
    __nv_bfloat162 lp; lp.x = l0; lp.y = l1;
    h = *reinterpret_cast<unsigned*>(&hp);
    l = *reinterpret_cast<unsigned*>(&lp);
}

__device__ __forceinline__ void mma_bf16(float* c, const unsigned* a, const unsigned* b)
{
    asm volatile(
        "mma.sync.aligned.m16n8k16.row.col.f32.bf16.bf16.f32 "
        "{%0,%1,%2,%3},{%4,%5,%6,%7},{%8,%9},{%0,%1,%2,%3};"
        : "+f"(c[0]), "+f"(c[1]), "+f"(c[2]), "+f"(c[3])
        : "r"(a[0]), "r"(a[1]), "r"(a[2]), "r"(a[3]), "r"(b[0]), "r"(b[1]));
}

__device__ __forceinline__ void cp16(unsigned dst, const void* src)
{
    asm volatile("cp.async.ca.shared.global [%0], [%1], 16;" :: "r"(dst), "l"(src));
}
__device__ __forceinline__ void cp_commit() { asm volatile("cp.async.commit_group;"); }
template<int N> __device__ __forceinline__ void cp_wait()
{ asm volatile("cp.async.wait_group %0;" :: "n"(N)); }

__device__ __forceinline__ void ldsm4(unsigned a, unsigned &r0, unsigned &r1,
                                      unsigned &r2, unsigned &r3)
{
    asm volatile("ldmatrix.sync.aligned.m8n8.x4.shared.b16 {%0,%1,%2,%3}, [%4];"
        : "=r"(r0), "=r"(r1), "=r"(r2), "=r"(r3) : "r"(a));
}
__device__ __forceinline__ void ldsm4t(unsigned a, unsigned &r0, unsigned &r1,
                                       unsigned &r2, unsigned &r3)
{
    asm volatile("ldmatrix.sync.aligned.m8n8.x4.trans.shared.b16 {%0,%1,%2,%3}, [%4];"
        : "=r"(r0), "=r"(r1), "=r"(r2), "=r"(r3) : "r"(a));
}

// ---------------- prep kernels ----------------------------------------------
__global__ void probe_mask_kernel(const unsigned int* __restrict__ m)
{
    __shared__ int s_ni, s_nf;
    if (threadIdx.x == 0) { s_ni = 0; s_nf = 0; }
    __syncthreads();
    int ni = 0, nf = 0;
    for (int i = threadIdx.x; i < 4096; i += 256) {
        unsigned w = m[i];
        if (w > 1u) ni = 1;
        if (w != 0u && w != 0x3F800000u) nf = 1;
    }
    if (ni) atomicOr(&s_ni, 1);
    if (nf) atomicOr(&s_nf, 1);
    __syncthreads();
    if (threadIdx.x == 0)
        g_mask_kind = (s_ni == 0) ? 0 : (s_nf == 0) ? 2 : 1;
}

__global__ void mask_pack_kernel(const void* __restrict__ maskp)
{
    int w = blockIdx.x*256 + threadIdx.x;     // 262144 words total
    int word = w & 63, row = w >> 6;          // row in [0, 4096)
    size_t off = (size_t)row*SEQ + word*32;
    unsigned bits = 0;
    if (g_mask_kind == 1) {
        const uchar4* p = (const uchar4*)((const unsigned char*)maskp + off);
#pragma unroll
        for (int i = 0; i < 8; i++) {
            uchar4 u4 = p[i];
            bits |= (u4.x ? 1u : 0u) << (i*4);
            bits |= (u4.y ? 1u : 0u) << (i*4+1);
            bits |= (u4.z ? 1u : 0u) << (i*4+2);
            bits |= (u4.w ? 1u : 0u) << (i*4+3);
        }
    } else {
        const uint4* p = (const uint4*)((const unsigned*)maskp + off);
#pragma unroll
        for (int i = 0; i < 8; i++) {
            uint4 u4 = p[i];
            bits |= (u4.x ? 1u : 0u) << (i*4);
            bits |= (u4.y ? 1u : 0u) << (i*4+1);
            bits |= (u4.z ? 1u : 0u) << (i*4+2);
            bits |= (u4.w ? 1u : 0u) << (i*4+3);
        }
    }
    g_mb[w] = bits;
}

__global__ void convert_hl_kernel(const float* __restrict__ src, int which, int nwords)
{
    unsigned *H, *L;
    if (which == 0)      { H = g_Xh;  L = g_Xl;  }
    else if (which == 1) { H = g_Wqh; L = g_Wql; }
    else                 { H = g_Pwh; L = g_Pwl; }
    int i = blockIdx.x*256 + threadIdx.x;
    if (i < nwords) {
        float2 v = ((const float2*)src)[i];
        unsigned h, l;
        cvt_pack(v.x, v.y, h, l);
        H[i] = h; L[i] = l;
    }
}

// ---------------- shared GEMM mainloop (bf16x3, ldmatrix, cp.async x2) ------
// tiles: BM=128, BN=64, BK=32; smem stage: A 128x128B + B 64x128B = 24KB; x2 = 48KB
// smem row = 128B: chunks 0-3 = hi k0..31, 4-7 = lo; phys chunk = logical ^ (row&7)
__device__ __forceinline__ void gemm_mainloop(
    const unsigned* __restrict__ Agh, const unsigned* __restrict__ Agl,
    const unsigned* __restrict__ Bgh, const unsigned* __restrict__ Bgl,
    unsigned* sm, int m0, int n0, float acc[2][4][4])
{
    const int tid = threadIdx.x;
    const int lane = tid & 31, warp = tid >> 5;
    const int warp_m = warp >> 1, warp_n = warp & 1;
    unsigned smb = (unsigned)__cvta_generic_to_shared(sm);

    auto stage = [&](int it, int buf) {
        unsigned ab = smb + buf*24576;
        unsigned bb = ab + 16384;
#pragma unroll
        for (int u = 0; u < 4; u++) {
            int ci = tid + u*256;
            int row = ci >> 3, cc = ci & 7, hl = cc >> 2, c = cc & 3;
            const unsigned* src = (hl ? Agl : Agh) + (size_t)(m0+row)*512 + it*16 + c*4;
            cp16(ab + row*128 + ((cc ^ (row&7))<<4), src);
        }
#pragma unroll
        for (int u = 0; u < 2; u++) {
            int ci = tid + u*256;
            int row = ci >> 3, cc = ci & 7, hl = cc >> 2, c = cc & 3;
            const unsigned* src = (hl ? Bgl : Bgh) + (size_t)(n0+row)*512 + it*16 + c*4;
            cp16(bb + row*128 + ((cc ^ (row&7))<<4), src);
        }
    };

    stage(0, 0); cp_commit();

    for (int it = 0; it < 32; it++) {
        __syncthreads();
        if (it + 1 < 32) stage(it+1, (it+1)&1);
        cp_commit();
        cp_wait<1>();
        __syncthreads();

        unsigned ab = smb + (it&1)*24576;
        unsigned bb = ab + 16384;
#pragma unroll
        for (int ks = 0; ks < 2; ks++) {
            unsigned ah[2][4], al[2][4], bh[4][2], bl[4][2];
#pragma unroll
            for (int mt = 0; mt < 2; mt++) {
                int row = warp_m*32 + mt*16 + (lane & 15);
                int ch = 2*ks + (lane >> 4);
                ldsm4(ab + row*128 + ((ch       ^ (row&7))<<4),
                      ah[mt][0], ah[mt][1], ah[mt][2], ah[mt][3]);
                ldsm4(ab + row*128 + (((ch + 4) ^ (row&7))<<4),
                      al[mt][0], al[mt][1], al[mt][2], al[mt][3]);
            }
#pragma unroll
            for (int ntp = 0; ntp < 2; ntp++) {
                int row = warp_n*32 + ntp*16 + (lane & 7) + ((lane & 16) >> 1);
                int ch = 2*ks + ((lane >> 3) & 1);
                unsigned r0, r1, r2, r3;
                ldsm4(bb + row*128 + ((ch ^ (row&7))<<4), r0, r1, r2, r3);
                bh[2*ntp][0] = r0; bh[2*ntp][1] = r1;
                bh[2*ntp+1][0] = r2; bh[2*ntp+1][1] = r3;
                ldsm4(bb + row*128 + (((ch + 4) ^ (row&7))<<4), r0, r1, r2, r3);
                bl[2*ntp][0] = r0; bl[2*ntp][1] = r1;
                bl[2*ntp+1][0] = r2; bl[2*ntp+1][1] = r3;
            }
#pragma unroll
            for (int mt = 0; mt < 2; mt++)
#pragma unroll
                for (int nt = 0; nt < 4; nt++) {
                    mma_bf16(acc[mt][nt], ah[mt], bh[nt]);
                    mma_bf16(acc[mt][nt], ah[mt], bl[nt]);
                    mma_bf16(acc[mt][nt], al[mt], bh[nt]);
                }
        }
    }
}

// packed bf16 hi/lo pair store for LN/V epilogue (d pairs via neighbor shuffle)
__device__ __forceinline__ void pack_store_pair(
    unsigned* __restrict__ H, unsigned* __restrict__ L,
    size_t wbase, int lane, float y1, float y2)
{
    float y1o = __shfl_xor_sync(0xffffffffu, y1, 1);
    float y2o = __shfl_xor_sync(0xffffffffu, y2, 1);
    if (!(lane & 1)) {
        unsigned h1, l1, h2, l2;
        cvt_pack(y1, y1o, h1, l1);
        cvt_pack(y2, y2o, h2, l2);
        H[wbase + (lane>>1)]      = h1;
        H[wbase + 16 + (lane>>1)] = h2;
        L[wbase + (lane>>1)]      = l1;
        L[wbase + 16 + (lane>>1)] = l2;
    }
}

// ---------------- kernel 1: QKV GEMM + fused layernorm -> packed bf16 -------
__global__ __launch_bounds__(256, 2) void qkv_gemm_ln_kernel(
    const float* __restrict__ qw, const float* __restrict__ qb,
    const float* __restrict__ kw, const float* __restrict__ kb)
{
    __shared__ unsigned sm[12288];
    const int tid = threadIdx.x;
    const int m0 = blockIdx.y * 128, n0 = blockIdx.x * 64;
    const int warp = tid >> 5, lane = tid & 31;
    const int warp_m = warp >> 1, warp_n = warp & 1;
    const int group = lane >> 2, tg = lane & 3;

    float acc[2][4][4];
#pragma unroll
    for (int mt = 0; mt < 2; mt++)
#pragma unroll
        for (int nt = 0; nt < 4; nt++)
#pragma unroll
            for (int j = 0; j < 4; j++) acc[mt][nt][j] = 0.f;

    gemm_mainloop(g_Xh, g_Xl, g_Wqh, g_Wql, sm, m0, n0, acc);

    const int s = n0 >> 10;
    const int h = (n0 & 1023) >> 6;
    float* et = (float*)sm;                  // [64][66]

    for (int rh = 0; rh < 2; rh++) {
        __syncthreads();
        if ((warp_m >> 1) == rh) {
#pragma unroll
            for (int mt = 0; mt < 2; mt++)
#pragma unroll
                for (int nt = 0; nt < 4; nt++) {
                    int r0 = warp_m*32 + mt*16 + group - rh*64;
                    int col = warp_n*32 + nt*8 + 2*tg;
                    *(float2*)&et[r0*66 + col] =
                        make_float2(acc[mt][nt][0], acc[mt][nt][1]);
                    *(float2*)&et[(r0+8)*66 + col] =
                        make_float2(acc[mt][nt][2], acc[mt][nt][3]);
                }
        }
        __syncthreads();
#pragma unroll
        for (int rr = 0; rr < 8; rr++) {
            int r  = warp*8 + rr;
            int gm = m0 + rh*64 + r;
            int bb = gm >> 11, n = gm & 2047;
            float v1 = et[r*66 + lane];
            float v2 = et[r*66 + lane + 32];
            size_t wbase = (((size_t)(bb*NHEADS + h))*SEQ + n)*32;
            if (s == 2) {
                pack_store_pair(g_vh, g_vl, wbase, lane, v1, v2);
            } else {
                float sum = v1 + v2, sq = v1*v1 + v2*v2;
#pragma unroll
                for (int o = 16; o; o >>= 1) {
                    sum += __shfl_xor_sync(0xffffffffu, sum, o);
                    sq  += __shfl_xor_sync(0xffffffffu, sq,  o);
                }
                float mean = sum * (1.f/64.f);
                float var  = sq  * (1.f/64.f) - mean*mean;
                float rstd = rsqrtf(var + 1e-5f);
                if (s == 0) {
                    float y1 = ((v1-mean)*rstd*qw[lane]    + qb[lane])    * 0.125f;
                    float y2 = ((v2-mean)*rstd*qw[lane+32] + qb[lane+32]) * 0.125f;
                    pack_store_pair(g_qh, g_ql, wbase, lane, y1, y2);
                } else {
                    float y1 = (v1-mean)*rstd*kw[lane]    + kb[lane];
                    float y2 = (v2-mean)*rstd*kw[lane+32] + kb[lane+32];
                    pack_store_pair(g_kh, g_kl, wbase, lane, y1, y2);
                }
            }
        }
    }
}

// ---------------- kernel 3: output projection + bias ------------------------
__global__ __launch_bounds__(256, 2) void proj_gemm_kernel(
    const float* __restrict__ bias, float* __restrict__ out)
{
    __shared__ unsigned sm[12288];
    const int tid = threadIdx.x;
    const int m0 = blockIdx.y * 128, n0 = blockIdx.x * 64;
    const int warp = tid >> 5, lane = tid & 31;
    const int warp_m = warp >> 1, warp_n = warp & 1;
    const int group = lane >> 2, tg = lane & 3;

    float acc[2][4][4];
#pragma unroll
    for (int mt = 0; mt < 2; mt++)
#pragma unroll
        for (int nt = 0; nt < 4; nt++)
#pragma unroll
            for (int j = 0; j < 4; j++) acc[mt][nt][j] = 0.f;

    gemm_mainloop(g_aoh, g_aol, g_Pwh, g_Pwl, sm, m0, n0, acc);

#pragma unroll
    for (int nt = 0; nt < 4; nt++) {
        int col = n0 + warp_n*32 + nt*8 + 2*tg;
        float b0 = bias[col], b1 = bias[col+1];
#pragma unroll
        for (int mt = 0; mt < 2; mt++) {
            int row = m0 + warp_m*32 + mt*16 + group;
            *(float2*)(out + (size_t)row*MDIM + col) =
                make_float2(acc[mt][nt][0] + b0, acc[mt][nt][1] + b1);
            *(float2*)(out + (size_t)(row+8)*MDIM + col) =
                make_float2(acc[mt][nt][2] + b0, acc[mt][nt][3] + b1);
        }
    }
}

// ---------------- kernel 2: flash attention (ldmatrix + cp.async) -----------
// dyn smem 64KB: 2 buffers x (Kh 8KB | Kl 8KB | Vh 8KB | Vl 8KB)
__global__ __launch_bounds__(256) void flash_attn_mma_kernel()
{
    extern __shared__ __align__(16) unsigned fsm[];
    const int tid = threadIdx.x;
    const int warp = tid >> 5, lane = tid & 31;
    const int group = lane >> 2, tg = lane & 3;
    const int q0 = blockIdx.x * 128, h = blockIdx.y, b = blockIdx.z;
    const int bhrow = (b*NHEADS + h)*SEQ;
    unsigned smb = (unsigned)__cvta_generic_to_shared(fsm);

    // ---- stage Q tile (128 rows, hi at +0, lo at +16KB) ----
#pragma unroll
    for (int u = 0; u < 8; u++) {
        int ci = tid + u*256;                 // 0..2047 chunks
        int hl = ci >> 10, wi = ci & 1023;
        int row = wi >> 3, c = wi & 7;
        const unsigned* src = (hl ? g_ql : g_qh) + (size_t)(bhrow + q0 + row)*32 + c*4;
        cp16(smb + hl*16384 + row*128 + ((c ^ (row&7))<<4), src);
    }
    cp_commit();
    cp_wait<0>();
    __syncthreads();

    unsigned qh[4][4], ql[4][4];
#pragma unroll
    for (int ks = 0; ks < 4; ks++) {
        int row = warp*16 + (lane & 15);
        int ch = 2*ks + (lane >> 4);
        unsigned a = row*128 + ((ch ^ (row&7))<<4);
        ldsm4(smb + a,         qh[ks][0], qh[ks][1], qh[ks][2], qh[ks][3]);
        ldsm4(smb + 16384 + a, ql[ks][0], ql[ks][1], ql[ks][2], ql[ks][3]);
    }
    __syncthreads();

    auto stageKV = [&](int kt, int buf) {
        unsigned base = smb + buf*32768;
#pragma unroll
        for (int u = 0; u < 8; u++) {
            int ci = tid + u*256;             // 0..2047
            int arr = ci >> 9, wi = ci & 511;
            int row = wi >> 3, c = wi & 7;
            const unsigned* sa;
            if (arr == 0) sa = g_kh; else if (arr == 1) sa = g_kl;
            else if (arr == 2) sa = g_vh; else sa = g_vl;
            const unsigned* src = sa + (size_t)(bhrow + kt*64 + row)*32 + c*4;
            cp16(base + arr*8192 + row*128 + ((c ^ (row&7))<<4), src);
        }
    };

    stageKV(0, 0); cp_commit();

    float m0r = MINIT, m1r = MINIT, l0r = 0.f, l1r = 0.f;
    float o[8][4];
#pragma unroll
    for (int nt = 0; nt < 8; nt++)
#pragma unroll
        for (int j = 0; j < 4; j++) o[nt][j] = 0.f;

    const int lr = warp*16 + group;
    const unsigned* mb0 = g_mb + (size_t)(b*SEQ + q0 + lr)*64;
    const unsigned* mb1 = g_mb + (size_t)(b*SEQ + q0 + lr + 8)*64;

    for (int kt = 0; kt < SEQ/64; kt++) {
        __syncthreads();
        if (kt + 1 < SEQ/64) stageKV(kt+1, (kt+1)&1);
        cp_commit();
        unsigned w0lo = mb0[kt*2], w0hi = mb0[kt*2+1];
        unsigned w1lo = mb1[kt*2], w1hi = mb1[kt*2+1];
        cp_wait<1>();
        __syncthreads();

        unsigned kb = smb + (kt&1)*32768;

        // ---- S = Q K^T (bf16x3) ----
        float s[8][4];
#pragma unroll
        for (int nt = 0; nt < 8; nt++)
#pragma unroll
            for (int j = 0; j < 4; j++) s[nt][j] = 0.f;
#pragma unroll
        for (int ks = 0; ks < 4; ks++) {
#pragma unroll
            for (int ntp = 0; ntp < 4; ntp++) {
                int row = ntp*16 + (lane & 7) + ((lane & 16) >> 1);
                int ch = 2*ks + ((lane >> 3) & 1);
                unsigned a = row*128 + ((ch ^ (row&7))<<4);
                unsigned bh0[2], bh1[2], bl0[2], bl1[2];
                ldsm4(kb + a,        bh0[0], bh0[1], bh1[0], bh1[1]);
                ldsm4(kb + 8192 + a, bl0[0], bl0[1], bl1[0], bl1[1]);
                mma_bf16(s[2*ntp],   qh[ks], bh0);
                mma_bf16(s[2*ntp],   qh[ks], bl0);
                mma_bf16(s[2*ntp],   ql[ks], bh0);
                mma_bf16(s[2*ntp+1], qh[ks], bh1);
                mma_bf16(s[2*ntp+1], qh[ks], bl1);
                mma_bf16(s[2*ntp+1], ql[ks], bh1);
            }
        }

        // ---- mask + online softmax ----
        float rm0 = MINIT, rm1 = MINIT;
#pragma unroll
        for (int nt = 0; nt < 8; nt++) {
            int kidx = nt*8 + 2*tg;
            unsigned wr0 = (nt < 4) ? w0lo : w0hi;
            unsigned wr1 = (nt < 4) ? w1lo : w1hi;
            int sh = kidx & 31;
            if ((wr0 >> sh) & 1)     s[nt][0] = MASKED;
            if ((wr0 >> (sh+1)) & 1) s[nt][1] = MASKED;
            if ((wr1 >> sh) & 1)     s[nt][2] = MASKED;
            if ((wr1 >> (sh+1)) & 1) s[nt][3] = MASKED;
            rm0 = fmaxf(rm0, fmaxf(s[nt][0], s[nt][1]));
            rm1 = fmaxf(rm1, fmaxf(s[nt][2], s[nt][3]));
        }
        rm0 = fmaxf(rm0, __shfl_xor_sync(0xffffffffu, rm0, 1));
        rm0 = fmaxf(rm0, __shfl_xor_sync(0xffffffffu, rm0, 2));
        rm1 = fmaxf(rm1, __shfl_xor_sync(0xffffffffu, rm1, 1));
        rm1 = fmaxf(rm1, __shfl_xor_sync(0xffffffffu, rm1, 2));
        float mn0 = fmaxf(m0r, rm0), mn1 = fmaxf(m1r, rm1);
        float c0 = __expf(m0r - mn0), c1 = __expf(m1r - mn1);
        m0r = mn0; m1r = mn1;

        float ls0 = 0.f, ls1 = 0.f;
#pragma unroll
        for (int nt = 0; nt < 8; nt++) {
            s[nt][0] = __expf(s[nt][0] - mn0);
            s[nt][1] = __expf(s[nt][1] - mn0);
            s[nt][2] = __expf(s[nt][2] - mn1);
            s[nt][3] = __expf(s[nt][3] - mn1);
            ls0 += s[nt][0] + s[nt][1];
            ls1 += s[nt][2] + s[nt][3];
        }
        ls0 += __shfl_xor_sync(0xffffffffu, ls0, 1);
        ls0 += __shfl_xor_sync(0xffffffffu, ls0, 2);
        ls1 += __shfl_xor_sync(0xffffffffu, ls1, 1);
        ls1 += __shfl_xor_sync(0xffffffffu, ls1, 2);
        l0r = l0r*c0 + ls0;
        l1r = l1r*c1 + ls1;
#pragma unroll
        for (int nt = 0; nt < 8; nt++) {
            o[nt][0] *= c0; o[nt][1] *= c0;
            o[nt][2] *= c1; o[nt][3] *= c1;
        }

        // ---- P fragments from S accumulators ----
        unsigned ph[4][4], pl[4][4];
#pragma unroll
        for (int j = 0; j < 4; j++) {
            cvt_pack(s[2*j][0],   s[2*j][1],   ph[j][0], pl[j][0]);
            cvt_pack(s[2*j][2],   s[2*j][3],   ph[j][1], pl[j][1]);
            cvt_pack(s[2*j+1][0], s[2*j+1][1], ph[j][2], pl[j][2]);
            cvt_pack(s[2*j+1][2], s[2*j+1][3], ph[j][3], pl[j][3]);
        }

        // ---- O += P V (V via ldmatrix.trans) ----
        unsigned vb = kb + 16384;
#pragma unroll
        for (int nt = 0; nt < 8; nt++) {
#pragma unroll
            for (int jp = 0; jp < 2; jp++) {
                int row = jp*32 + lane;
                unsigned a = vb + row*128 + ((nt ^ (row&7))<<4);
                unsigned vh0[2], vh1[2], vl0[2], vl1[2];
                ldsm4t(a,        vh0[0], vh0[1], vh1[0], vh1[1]);
                ldsm4t(a + 8192, vl0[0], vl0[1], vl1[0], vl1[1]);
                mma_bf16(o[nt], ph[2*jp],   vh0);
                mma_bf16(o[nt], ph[2*jp],   vl0);
                mma_bf16(o[nt], pl[2*jp],   vh0);
                mma_bf16(o[nt], ph[2*jp+1], vh1);
                mma_bf16(o[nt], ph[2*jp+1], vl1);
                mma_bf16(o[nt], pl[2*jp+1], vh1);
            }
        }
    }

    // ---- finalize: pack to bf16 hi/lo ao ----
    const int row0 = q0 + warp*16 + group;
    float inv0 = 1.f / l0r, inv1 = 1.f / l1r;
#pragma unroll
    for (int nt = 0; nt < 8; nt++) {
        int widx = h*32 + nt*4 + tg;
        unsigned hh, ll;
        cvt_pack(o[nt][0]*inv0, o[nt][1]*inv0, hh, ll);
        g_aoh[(size_t)(b*SEQ + row0)*512 + widx] = hh;
        g_aol[(size_t)(b*SEQ + row0)*512 + widx] = ll;
        cvt_pack(o[nt][2]*inv1, o[nt][3]*inv1, hh, ll);
        g_aoh[(size_t)(b*SEQ + row0 + 8)*512 + widx] = hh;
        g_aol[(size_t)(b*SEQ + row0 + 8)*512 + widx] = ll;
    }
}

// ---------------- launch ----------------------------------------------------
extern "C" void kernel_launch(void* const* d_in, const int* in_sizes, int n_in,
                              void* d_out, int out_size)
{
    const float* x      = (const float*)d_in[0];
    const void*  mask   = d_in[1];
    const float* qkv_w  = (const float*)d_in[2];
    const float* q_nw   = (const float*)d_in[3];
    const float* q_nb   = (const float*)d_in[4];
    const float* k_nw   = (const float*)d_in[5];
    const float* k_nb   = (const float*)d_in[6];
    const float* proj_w = (const float*)d_in[7];
    const float* proj_b = (const float*)d_in[8];
    float* out = (float*)d_out;

    probe_mask_kernel<<<1, 256>>>((const unsigned int*)mask);
    mask_pack_kernel<<<1024, 256>>>(mask);

    convert_hl_kernel<<<8192, 256>>>(x,      0, 4096*512);
    convert_hl_kernel<<<6144, 256>>>(qkv_w,  1, 3072*512);
    convert_hl_kernel<<<2048, 256>>>(proj_w, 2, 1024*512);

    qkv_gemm_ln_kernel<<<dim3(48, 32), 256>>>(q_nw, q_nb, k_nw, k_nb);

    cudaFuncSetAttribute(flash_attn_mma_kernel,
                         cudaFuncAttributeMaxDynamicSharedMemorySize, 65536);
    flash_attn_mma_kernel<<<dim3(16, NHEADS, BATCH), 256, 65536>>>();

    proj_gemm_kernel<<<dim3(16, 32), 256>>>(proj_b, out);
}

// round 7
// speedup vs baseline: 2.8128x; 1.1585x over previous
#include <cuda_runtime.h>
#include <cuda_bf16.h>
#include <math.h>

#define SEQ   2048
#define BATCH 2
#define NHEADS 16
#define HDIM  64
#define MDIM  1024

#define MASKED (-2e30f)
#define MINIT  (-1e30f)

// ---------------- scratch (device globals; no allocations allowed) ----------
__device__ __align__(16) unsigned g_Xh[4096*512],  g_Xl[4096*512];    // X bf16 hi/lo
__device__ __align__(16) unsigned g_Wqh[3072*512], g_Wql[3072*512];   // qkv_w
__device__ __align__(16) unsigned g_Pwh[1024*512], g_Pwl[1024*512];   // proj_w
__device__ __align__(16) unsigned g_qh[65536*32],  g_ql[65536*32];    // (b,h,n) rows of 64 d
__device__ __align__(16) unsigned g_kh[65536*32],  g_kl[65536*32];
__device__ __align__(16) unsigned g_vh[65536*32],  g_vl[65536*32];
__device__ __align__(16) unsigned g_aoh[4096*512], g_aol[4096*512];   // attn out bf16 hi/lo
__device__ unsigned g_mb[4096*64];                                    // mask bits
__device__ int g_mask_kind;                                           // 0/2=word, 1=byte

// ---------------- helpers ----------------------------------------------------
__device__ __forceinline__ void cvt_pack(float x0, float x1, unsigned &h, unsigned &l)
{
    __nv_bfloat16 h0 = __float2bfloat16_rn(x0);
    __nv_bfloat16 h1 = __float2bfloat16_rn(x1);
    __nv_bfloat16 l0 = __float2bfloat16_rn(x0 - __bfloat162float(h0));
    __nv_bfloat16 l1 = __float2bfloat16_rn(x1 - __bfloat162float(h1));
    __nv_bfloat162 hp; hp.x = h0; hp.y = h1;
    __nv_bfloat162 lp; lp.x = l0; lp.y = l1;
    h = *reinterpret_cast<unsigned*>(&hp);
    l = *reinterpret_cast<unsigned*>(&lp);
}

__device__ __forceinline__ void mma_bf16(float* c, const unsigned* a, const unsigned* b)
{
    asm volatile(
        "mma.sync.aligned.m16n8k16.row.col.f32.bf16.bf16.f32 "
        "{%0,%1,%2,%3},{%4,%5,%6,%7},{%8,%9},{%0,%1,%2,%3};"
        : "+f"(c[0]), "+f"(c[1]), "+f"(c[2]), "+f"(c[3])
        : "r"(a[0]), "r"(a[1]), "r"(a[2]), "r"(a[3]), "r"(b[0]), "r"(b[1]));
}

__device__ __forceinline__ void cp16(unsigned dst, const void* src)
{
    asm volatile("cp.async.cg.shared.global [%0], [%1], 16;" :: "r"(dst), "l"(src));
}
__device__ __forceinline__ void cp_commit() { asm volatile("cp.async.commit_group;"); }
template<int N> __device__ __forceinline__ void cp_wait()
{ asm volatile("cp.async.wait_group %0;" :: "n"(N)); }

__device__ __forceinline__ void ldsm4(unsigned a, unsigned &r0, unsigned &r1,
                                      unsigned &r2, unsigned &r3)
{
    asm volatile("ldmatrix.sync.aligned.m8n8.x4.shared.b16 {%0,%1,%2,%3}, [%4];"
        : "=r"(r0), "=r"(r1), "=r"(r2), "=r"(r3) : "r"(a));
}
__device__ __forceinline__ void ldsm4t(unsigned a, unsigned &r0, unsigned &r1,
                                       unsigned &r2, unsigned &r3)
{
    asm volatile("ldmatrix.sync.aligned.m8n8.x4.trans.shared.b16 {%0,%1,%2,%3}, [%4];"
        : "=r"(r0), "=r"(r1), "=r"(r2), "=r"(r3) : "r"(a));
}

// ---------------- prep kernels ----------------------------------------------
__global__ void probe_mask_kernel(const unsigned int* __restrict__ m)
{
    __shared__ int s_ni, s_nf;
    if (threadIdx.x == 0) { s_ni = 0; s_nf = 0; }
    __syncthreads();
    int ni = 0, nf = 0;
    for (int i = threadIdx.x; i < 4096; i += 256) {
        unsigned w = m[i];
        if (w > 1u) ni = 1;
        if (w != 0u && w != 0x3F800000u) nf = 1;
    }
    if (ni) atomicOr(&s_ni, 1);
    if (nf) atomicOr(&s_nf, 1);
    __syncthreads();
    if (threadIdx.x == 0)
        g_mask_kind = (s_ni == 0) ? 0 : (s_nf == 0) ? 2 : 1;
}

__global__ void mask_pack_kernel(const void* __restrict__ maskp)
{
    int w = blockIdx.x*256 + threadIdx.x;     // 262144 words total
    int word = w & 63, row = w >> 6;
    size_t off = (size_t)row*SEQ + word*32;
    unsigned bits = 0;
    if (g_mask_kind == 1) {
        const uchar4* p = (const uchar4*)((const unsigned char*)maskp + off);
#pragma unroll
        for (int i = 0; i < 8; i++) {
            uchar4 u4 = p[i];
            bits |= (u4.x ? 1u : 0u) << (i*4);
            bits |= (u4.y ? 1u : 0u) << (i*4+1);
            bits |= (u4.z ? 1u : 0u) << (i*4+2);
            bits |= (u4.w ? 1u : 0u) << (i*4+3);
        }
    } else {
        const uint4* p = (const uint4*)((const unsigned*)maskp + off);
#pragma unroll
        for (int i = 0; i < 8; i++) {
            uint4 u4 = p[i];
            bits |= (u4.x ? 1u : 0u) << (i*4);
            bits |= (u4.y ? 1u : 0u) << (i*4+1);
            bits |= (u4.z ? 1u : 0u) << (i*4+2);
            bits |= (u4.w ? 1u : 0u) << (i*4+3);
        }
    }
    g_mb[w] = bits;
}

// fused: converts x (2M f2), qkv_w (1.5M f2), proj_w (0.5M f2) in one launch
#define NW_X   (4096*512)
#define NW_WQ  (3072*512)
#define NW_PW  (1024*512)
__global__ void convert_all_kernel(const float* __restrict__ x,
                                   const float* __restrict__ qkv_w,
                                   const float* __restrict__ proj_w)
{
    int i = blockIdx.x*256 + threadIdx.x;
    const float* src; unsigned *H, *L; int idx;
    if (i < NW_X)                 { src = x;      H = g_Xh;  L = g_Xl;  idx = i; }
    else if (i < NW_X + NW_WQ)    { src = qkv_w;  H = g_Wqh; L = g_Wql; idx = i - NW_X; }
    else                          { src = proj_w; H = g_Pwh; L = g_Pwl; idx = i - NW_X - NW_WQ; }
    float2 v = ((const float2*)src)[idx];
    unsigned h, l;
    cvt_pack(v.x, v.y, h, l);
    H[idx] = h; L[idx] = l;
}

// ---------------- shared GEMM mainloop (single-sync 2-stage pipeline) -------
// tiles: BM=128, BN=64, BK=32; stage: A 128x128B + B 64x128B = 24KB; x2 = 48KB
// smem row = 128B: chunks 0-3 = hi k0..31, 4-7 = lo; phys chunk = logical ^ (row&7)
__device__ __forceinline__ void gemm_mainloop(
    const unsigned* __restrict__ Agh, const unsigned* __restrict__ Agl,
    const unsigned* __restrict__ Bgh, const unsigned* __restrict__ Bgl,
    unsigned* sm, int m0, int n0, float acc[2][4][4])
{
    const int tid = threadIdx.x;
    const int lane = tid & 31, warp = tid >> 5;
    const int warp_m = warp >> 1, warp_n = warp & 1;
    unsigned smb = (unsigned)__cvta_generic_to_shared(sm);

    auto stage = [&](int it, int buf) {
        unsigned ab = smb + buf*24576;
        unsigned bb = ab + 16384;
#pragma unroll
        for (int u = 0; u < 4; u++) {
            int ci = tid + u*256;
            int row = ci >> 3, cc = ci & 7, hl = cc >> 2, c = cc & 3;
            const unsigned* src = (hl ? Agl : Agh) + (size_t)(m0+row)*512 + it*16 + c*4;
            cp16(ab + row*128 + ((cc ^ (row&7))<<4), src);
        }
#pragma unroll
        for (int u = 0; u < 2; u++) {
            int ci = tid + u*256;
            int row = ci >> 3, cc = ci & 7, hl = cc >> 2, c = cc & 3;
            const unsigned* src = (hl ? Bgl : Bgh) + (size_t)(n0+row)*512 + it*16 + c*4;
            cp16(bb + row*128 + ((cc ^ (row&7))<<4), src);
        }
    };

    stage(0, 0); cp_commit();

    for (int it = 0; it < 32; it++) {
        cp_wait<0>();
        __syncthreads();
        // issue next stage AFTER the barrier: race-free (all warps finished
        // reading this buffer at it-1) and overlaps the whole consume phase.
        if (it + 1 < 32) { stage(it+1, (it+1)&1); cp_commit(); }

        unsigned ab = smb + (it&1)*24576;
        unsigned bb = ab + 16384;
#pragma unroll
        for (int ks = 0; ks < 2; ks++) {
            unsigned ah[2][4], al[2][4], bh[4][2], bl[4][2];
#pragma unroll
            for (int mt = 0; mt < 2; mt++) {
                int row = warp_m*32 + mt*16 + (lane & 15);
                int ch = 2*ks + (lane >> 4);
                ldsm4(ab + row*128 + ((ch       ^ (row&7))<<4),
                      ah[mt][0], ah[mt][1], ah[mt][2], ah[mt][3]);
                ldsm4(ab + row*128 + (((ch + 4) ^ (row&7))<<4),
                      al[mt][0], al[mt][1], al[mt][2], al[mt][3]);
            }
#pragma unroll
            for (int ntp = 0; ntp < 2; ntp++) {
                int row = warp_n*32 + ntp*16 + (lane & 7) + ((lane & 16) >> 1);
                int ch = 2*ks + ((lane >> 3) & 1);
                unsigned r0, r1, r2, r3;
                ldsm4(bb + row*128 + ((ch ^ (row&7))<<4), r0, r1, r2, r3);
                bh[2*ntp][0] = r0; bh[2*ntp][1] = r1;
                bh[2*ntp+1][0] = r2; bh[2*ntp+1][1] = r3;
                ldsm4(bb + row*128 + (((ch + 4) ^ (row&7))<<4), r0, r1, r2, r3);
                bl[2*ntp][0] = r0; bl[2*ntp][1] = r1;
                bl[2*ntp+1][0] = r2; bl[2*ntp+1][1] = r3;
            }
#pragma unroll
            for (int mt = 0; mt < 2; mt++)
#pragma unroll
                for (int nt = 0; nt < 4; nt++) {
                    mma_bf16(acc[mt][nt], ah[mt], bh[nt]);
                    mma_bf16(acc[mt][nt], ah[mt], bl[nt]);
                    mma_bf16(acc[mt][nt], al[mt], bh[nt]);
                }
        }
    }
}

// packed bf16 hi/lo pair store for LN/V epilogue (d pairs via neighbor shuffle)
__device__ __forceinline__ void pack_store_pair(
    unsigned* __restrict__ H, unsigned* __restrict__ L,
    size_t wbase, int lane, float y1, float y2)
{
    float y1o = __shfl_xor_sync(0xffffffffu, y1, 1);
    float y2o = __shfl_xor_sync(0xffffffffu, y2, 1);
    if (!(lane & 1)) {
        unsigned h1, l1, h2, l2;
        cvt_pack(y1, y1o, h1, l1);
        cvt_pack(y2, y2o, h2, l2);
        H[wbase + (lane>>1)]      = h1;
        H[wbase + 16 + (lane>>1)] = h2;
        L[wbase + (lane>>1)]      = l1;
        L[wbase + 16 + (lane>>1)] = l2;
    }
}

// ---------------- kernel 1: QKV GEMM + fused layernorm -> packed bf16 -------
__global__ __launch_bounds__(256, 2) void qkv_gemm_ln_kernel(
    const float* __restrict__ qw, const float* __restrict__ qb,
    const float* __restrict__ kw, const float* __restrict__ kb)
{
    __shared__ unsigned sm[12288];
    const int tid = threadIdx.x;
    const int m0 = blockIdx.y * 128, n0 = blockIdx.x * 64;
    const int warp = tid >> 5, lane = tid & 31;
    const int warp_m = warp >> 1, warp_n = warp & 1;
    const int group = lane >> 2, tg = lane & 3;

    float acc[2][4][4];
#pragma unroll
    for (int mt = 0; mt < 2; mt++)
#pragma unroll
        for (int nt = 0; nt < 4; nt++)
#pragma unroll
            for (int j = 0; j < 4; j++) acc[mt][nt][j] = 0.f;

    gemm_mainloop(g_Xh, g_Xl, g_Wqh, g_Wql, sm, m0, n0, acc);

    const int s = n0 >> 10;
    const int h = (n0 & 1023) >> 6;
    float* et = (float*)sm;                  // [64][66]

    for (int rh = 0; rh < 2; rh++) {
        __syncthreads();
        if ((warp_m >> 1) == rh) {
#pragma unroll
            for (int mt = 0; mt < 2; mt++)
#pragma unroll
                for (int nt = 0; nt < 4; nt++) {
                    int r0 = warp_m*32 + mt*16 + group - rh*64;
                    int col = warp_n*32 + nt*8 + 2*tg;
                    *(float2*)&et[r0*66 + col] =
                        make_float2(acc[mt][nt][0], acc[mt][nt][1]);
                    *(float2*)&et[(r0+8)*66 + col] =
                        make_float2(acc[mt][nt][2], acc[mt][nt][3]);
                }
        }
        __syncthreads();
#pragma unroll
        for (int rr = 0; rr < 8; rr++) {
            int r  = warp*8 + rr;
            int gm = m0 + rh*64 + r;
            int bb = gm >> 11, n = gm & 2047;
            float v1 = et[r*66 + lane];
            float v2 = et[r*66 + lane + 32];
            size_t wbase = (((size_t)(bb*NHEADS + h))*SEQ + n)*32;
            if (s == 2) {
                pack_store_pair(g_vh, g_vl, wbase, lane, v1, v2);
            } else {
                float sum = v1 + v2, sq = v1*v1 + v2*v2;
#pragma unroll
                for (int o = 16; o; o >>= 1) {
                    sum += __shfl_xor_sync(0xffffffffu, sum, o);
                    sq  += __shfl_xor_sync(0xffffffffu, sq,  o);
                }
                float mean = sum * (1.f/64.f);
                float var  = sq  * (1.f/64.f) - mean*mean;
                float rstd = rsqrtf(var + 1e-5f);
                if (s == 0) {
                    float y1 = ((v1-mean)*rstd*qw[lane]    + qb[lane])    * 0.125f;
                    float y2 = ((v2-mean)*rstd*qw[lane+32] + qb[lane+32]) * 0.125f;
                    pack_store_pair(g_qh, g_ql, wbase, lane, y1, y2);
                } else {
                    float y1 = (v1-mean)*rstd*kw[lane]    + kb[lane];
                    float y2 = (v2-mean)*rstd*kw[lane+32] + kb[lane+32];
                    pack_store_pair(g_kh, g_kl, wbase, lane, y1, y2);
                }
            }
        }
    }
}

// ---------------- kernel 3: output projection + bias ------------------------
__global__ __launch_bounds__(256, 2) void proj_gemm_kernel(
    const float* __restrict__ bias, float* __restrict__ out)
{
    __shared__ unsigned sm[12288];
    const int tid = threadIdx.x;
    const int m0 = blockIdx.y * 128, n0 = blockIdx.x * 64;
    const int warp = tid >> 5, lane = tid & 31;
    const int warp_m = warp >> 1, warp_n = warp & 1;
    const int group = lane >> 2, tg = lane & 3;

    float acc[2][4][4];
#pragma unroll
    for (int mt = 0; mt < 2; mt++)
#pragma unroll
        for (int nt = 0; nt < 4; nt++)
#pragma unroll
            for (int j = 0; j < 4; j++) acc[mt][nt][j] = 0.f;

    gemm_mainloop(g_aoh, g_aol, g_Pwh, g_Pwl, sm, m0, n0, acc);

#pragma unroll
    for (int nt = 0; nt < 4; nt++) {
        int col = n0 + warp_n*32 + nt*8 + 2*tg;
        float b0 = bias[col], b1 = bias[col+1];
#pragma unroll
        for (int mt = 0; mt < 2; mt++) {
            int row = m0 + warp_m*32 + mt*16 + group;
            *(float2*)(out + (size_t)row*MDIM + col) =
                make_float2(acc[mt][nt][0] + b0, acc[mt][nt][1] + b1);
            *(float2*)(out + (size_t)(row+8)*MDIM + col) =
                make_float2(acc[mt][nt][2] + b0, acc[mt][nt][3] + b1);
        }
    }
}

// ---------------- kernel 2: flash attention (single-sync pipeline) ----------
// dyn smem 64KB: 2 buffers x (Kh 8KB | Kl 8KB | Vh 8KB | Vl 8KB)
__global__ __launch_bounds__(256) void flash_attn_mma_kernel()
{
    extern __shared__ __align__(16) unsigned fsm[];
    const int tid = threadIdx.x;
    const int warp = tid >> 5, lane = tid & 31;
    const int group = lane >> 2, tg = lane & 3;
    const int q0 = blockIdx.x * 128, h = blockIdx.y, b = blockIdx.z;
    const int bhrow = (b*NHEADS + h)*SEQ;
    unsigned smb = (unsigned)__cvta_generic_to_shared(fsm);

    // ---- stage Q tile (128 rows, hi at +0, lo at +16KB) ----
#pragma unroll
    for (int u = 0; u < 8; u++) {
        int ci = tid + u*256;
        int hl = ci >> 10, wi = ci & 1023;
        int row = wi >> 3, c = wi & 7;
        const unsigned* src = (hl ? g_ql : g_qh) + (size_t)(bhrow + q0 + row)*32 + c*4;
        cp16(smb + hl*16384 + row*128 + ((c ^ (row&7))<<4), src);
    }
    cp_commit();
    cp_wait<0>();
    __syncthreads();

    unsigned qh[4][4], ql[4][4];
#pragma unroll
    for (int ks = 0; ks < 4; ks++) {
        int row = warp*16 + (lane & 15);
        int ch = 2*ks + (lane >> 4);
        unsigned a = row*128 + ((ch ^ (row&7))<<4);
        ldsm4(smb + a,         qh[ks][0], qh[ks][1], qh[ks][2], qh[ks][3]);
        ldsm4(smb + 16384 + a, ql[ks][0], ql[ks][1], ql[ks][2], ql[ks][3]);
    }
    __syncthreads();

    auto stageKV = [&](int kt, int buf) {
        unsigned base = smb + buf*32768;
#pragma unroll
        for (int u = 0; u < 8; u++) {
            int ci = tid + u*256;
            int arr = ci >> 9, wi = ci & 511;
            int row = wi >> 3, c = wi & 7;
            const unsigned* sa;
            if (arr == 0) sa = g_kh; else if (arr == 1) sa = g_kl;
            else if (arr == 2) sa = g_vh; else sa = g_vl;
            const unsigned* src = sa + (size_t)(bhrow + kt*64 + row)*32 + c*4;
            cp16(base + arr*8192 + row*128 + ((c ^ (row&7))<<4), src);
        }
    };

    stageKV(0, 0); cp_commit();

    float m0r = MINIT, m1r = MINIT, l0r = 0.f, l1r = 0.f;
    float o[8][4];
#pragma unroll
    for (int nt = 0; nt < 8; nt++)
#pragma unroll
        for (int j = 0; j < 4; j++) o[nt][j] = 0.f;

    const int lr = warp*16 + group;
    const unsigned* mb0 = g_mb + (size_t)(b*SEQ + q0 + lr)*64;
    const unsigned* mb1 = g_mb + (size_t)(b*SEQ + q0 + lr + 8)*64;

    for (int kt = 0; kt < SEQ/64; kt++) {
        unsigned w0lo = mb0[kt*2], w0hi = mb0[kt*2+1];
        unsigned w1lo = mb1[kt*2], w1hi = mb1[kt*2+1];
        cp_wait<0>();
        __syncthreads();
        if (kt + 1 < SEQ/64) { stageKV(kt+1, (kt+1)&1); cp_commit(); }

        unsigned kb = smb + (kt&1)*32768;

        // ---- S = Q K^T (bf16x3) ----
        float s[8][4];
#pragma unroll
        for (int nt = 0; nt < 8; nt++)
#pragma unroll
            for (int j = 0; j < 4; j++) s[nt][j] = 0.f;
#pragma unroll
        for (int ks = 0; ks < 4; ks++) {
#pragma unroll
            for (int ntp = 0; ntp < 4; ntp++) {
                int row = ntp*16 + (lane & 7) + ((lane & 16) >> 1);
                int ch = 2*ks + ((lane >> 3) & 1);
                unsigned a = row*128 + ((ch ^ (row&7))<<4);
                unsigned bh0[2], bh1[2], bl0[2], bl1[2];
                ldsm4(kb + a,        bh0[0], bh0[1], bh1[0], bh1[1]);
                ldsm4(kb + 8192 + a, bl0[0], bl0[1], bl1[0], bl1[1]);
                mma_bf16(s[2*ntp],   qh[ks], bh0);
                mma_bf16(s[2*ntp],   qh[ks], bl0);
                mma_bf16(s[2*ntp],   ql[ks], bh0);
                mma_bf16(s[2*ntp+1], qh[ks], bh1);
                mma_bf16(s[2*ntp+1], qh[ks], bl1);
                mma_bf16(s[2*ntp+1], ql[ks], bh1);
            }
        }

        // ---- mask + online softmax ----
        float rm0 = MINIT, rm1 = MINIT;
#pragma unroll
        for (int nt = 0; nt < 8; nt++) {
            int kidx = nt*8 + 2*tg;
            unsigned wr0 = (nt < 4) ? w0lo : w0hi;
            unsigned wr1 = (nt < 4) ? w1lo : w1hi;
            int sh = kidx & 31;
            if ((wr0 >> sh) & 1)     s[nt][0] = MASKED;
            if ((wr0 >> (sh+1)) & 1) s[nt][1] = MASKED;
            if ((wr1 >> sh) & 1)     s[nt][2] = MASKED;
            if ((wr1 >> (sh+1)) & 1) s[nt][3] = MASKED;
            rm0 = fmaxf(rm0, fmaxf(s[nt][0], s[nt][1]));
            rm1 = fmaxf(rm1, fmaxf(s[nt][2], s[nt][3]));
        }
        rm0 = fmaxf(rm0, __shfl_xor_sync(0xffffffffu, rm0, 1));
        rm0 = fmaxf(rm0, __shfl_xor_sync(0xffffffffu, rm0, 2));
        rm1 = fmaxf(rm1, __shfl_xor_sync(0xffffffffu, rm1, 1));
        rm1 = fmaxf(rm1, __shfl_xor_sync(0xffffffffu, rm1, 2));
        float mn0 = fmaxf(m0r, rm0), mn1 = fmaxf(m1r, rm1);
        float c0 = __expf(m0r - mn0), c1 = __expf(m1r - mn1);
        m0r = mn0; m1r = mn1;

        float ls0 = 0.f, ls1 = 0.f;
#pragma unroll
        for (int nt = 0; nt < 8; nt++) {
            s[nt][0] = __expf(s[nt][0] - mn0);
            s[nt][1] = __expf(s[nt][1] - mn0);
            s[nt][2] = __expf(s[nt][2] - mn1);
            s[nt][3] = __expf(s[nt][3] - mn1);
            ls0 += s[nt][0] + s[nt][1];
            ls1 += s[nt][2] + s[nt][3];
        }
        ls0 += __shfl_xor_sync(0xffffffffu, ls0, 1);
        ls0 += __shfl_xor_sync(0xffffffffu, ls0, 2);
        ls1 += __shfl_xor_sync(0xffffffffu, ls1, 1);
        ls1 += __shfl_xor_sync(0xffffffffu, ls1, 2);
        l0r = l0r*c0 + ls0;
        l1r = l1r*c1 + ls1;
#pragma unroll
        for (int nt = 0; nt < 8; nt++) {
            o[nt][0] *= c0; o[nt][1] *= c0;
            o[nt][2] *= c1; o[nt][3] *= c1;
        }

        // ---- P fragments from S accumulators ----
        unsigned ph[4][4], pl[4][4];
#pragma unroll
        for (int j = 0; j < 4; j++) {
            cvt_pack(s[2*j][0],   s[2*j][1],   ph[j][0], pl[j][0]);
            cvt_pack(s[2*j][2],   s[2*j][3],   ph[j][1], pl[j][1]);
            cvt_pack(s[2*j+1][0], s[2*j+1][1], ph[j][2], pl[j][2]);
            cvt_pack(s[2*j+1][2], s[2*j+1][3], ph[j][3], pl[j][3]);
        }

        // ---- O += P V (V via ldmatrix.trans) ----
        unsigned vb = kb + 16384;
#pragma unroll
        for (int nt = 0; nt < 8; nt++) {
#pragma unroll
            for (int jp = 0; jp < 2; jp++) {
                int row = jp*32 + lane;
                unsigned a = vb + row*128 + ((nt ^ (row&7))<<4);
                unsigned vh0[2], vh1[2], vl0[2], vl1[2];
                ldsm4t(a,        vh0[0], vh0[1], vh1[0], vh1[1]);
                ldsm4t(a + 8192, vl0[0], vl0[1], vl1[0], vl1[1]);
                mma_bf16(o[nt], ph[2*jp],   vh0);
                mma_bf16(o[nt], ph[2*jp],   vl0);
                mma_bf16(o[nt], pl[2*jp],   vh0);
                mma_bf16(o[nt], ph[2*jp+1], vh1);
                mma_bf16(o[nt], ph[2*jp+1], vl1);
                mma_bf16(o[nt], pl[2*jp+1], vh1);
            }
        }
    }

    // ---- finalize: pack to bf16 hi/lo ao ----
    const int row0 = q0 + warp*16 + group;
    float inv0 = 1.f / l0r, inv1 = 1.f / l1r;
#pragma unroll
    for (int nt = 0; nt < 8; nt++) {
        int widx = h*32 + nt*4 + tg;
        unsigned hh, ll;
        cvt_pack(o[nt][0]*inv0, o[nt][1]*inv0, hh, ll);
        g_aoh[(size_t)(b*SEQ + row0)*512 + widx] = hh;
        g_aol[(size_t)(b*SEQ + row0)*512 + widx] = ll;
        cvt_pack(o[nt][2]*inv1, o[nt][3]*inv1, hh, ll);
        g_aoh[(size_t)(b*SEQ + row0 + 8)*512 + widx] = hh;
        g_aol[(size_t)(b*SEQ + row0 + 8)*512 + widx] = ll;
    }
}

// ---------------- launch ----------------------------------------------------
extern "C" void kernel_launch(void* const* d_in, const int* in_sizes, int n_in,
                              void* d_out, int out_size)
{
    const float* x      = (const float*)d_in[0];
    const void*  mask   = d_in[1];
    const float* qkv_w  = (const float*)d_in[2];
    const float* q_nw   = (const float*)d_in[3];
    const float* q_nb   = (const float*)d_in[4];
    const float* k_nw   = (const float*)d_in[5];
    const float* k_nb   = (const float*)d_in[6];
    const float* proj_w = (const float*)d_in[7];
    const float* proj_b = (const float*)d_in[8];
    float* out = (float*)d_out;

    probe_mask_kernel<<<1, 256>>>((const unsigned int*)mask);
    mask_pack_kernel<<<1024, 256>>>(mask);
    convert_all_kernel<<<(NW_X + NW_WQ + NW_PW)/256, 256>>>(x, qkv_w, proj_w);

    qkv_gemm_ln_kernel<<<dim3(48, 32), 256>>>(q_nw, q_nb, k_nw, k_nb);

    cudaFuncSetAttribute(flash_attn_mma_kernel,
                         cudaFuncAttributeMaxDynamicSharedMemorySize, 65536);
    flash_attn_mma_kernel<<<dim3(16, NHEADS, BATCH), 256, 65536>>>();

    proj_gemm_kernel<<<dim3(16, 32), 256>>>(proj_b, out);
}